// round 2
// baseline (speedup 1.0000x reference)
#include <cuda_runtime.h>
#include <math.h>

#define BB 8
#define LL 1000
#define DD 512
#define HH 8
#define DKK 64
#define NTOK (BB*LL)
#define RELN (2*LL-1)

typedef unsigned long long u64;

// packed f32x2 helpers (FFMA2 path — ptxas never emits these from plain C++)
__device__ __forceinline__ void ffma2(u64& c, u64 a, u64 b) {
    asm("fma.rn.f32x2 %0, %1, %2, %0;" : "+l"(c) : "l"(a), "l"(b));
}
__device__ __forceinline__ void fmul2(u64& c, u64 a) {
    asm("mul.rn.f32x2 %0, %0, %1;" : "+l"(c) : "l"(a));
}
__device__ __forceinline__ u64 pack2(float x, float y) {
    u64 r; asm("mov.b64 %0, {%1, %2};" : "=l"(r) : "f"(x), "f"(y)); return r;
}
__device__ __forceinline__ float2 unpack2(u64 v) {
    float2 r; asm("mov.b64 {%0, %1}, %2;" : "=f"(r.x), "=f"(r.y) : "l"(v)); return r;
}

// scratch (device globals: no allocations allowed)
__device__ float g_xn[NTOK*DD];
__device__ float g_q[NTOK*DD];   // layout (B,H,L,dk)
__device__ float g_k[NTOK*DD];
__device__ float g_v[NTOK*DD];
__device__ float g_ctx[NTOK*DD]; // layout (B,L,D)

// ---------------------------------------------------------------- LayerNorm
__global__ __launch_bounds__(128) void ln_kernel(const float* __restrict__ x,
                                                 const float* __restrict__ gamma,
                                                 const float* __restrict__ beta)
{
    int tok = blockIdx.x;
    int tid = threadIdx.x;
    const float4 v = reinterpret_cast<const float4*>(x + (size_t)tok * DD)[tid];
    float s  = v.x + v.y + v.z + v.w;
    float ss = v.x*v.x + v.y*v.y + v.z*v.z + v.w*v.w;
#pragma unroll
    for (int o = 16; o; o >>= 1) {
        s  += __shfl_xor_sync(0xffffffffu, s,  o);
        ss += __shfl_xor_sync(0xffffffffu, ss, o);
    }
    __shared__ float sh[8];
    int w = tid >> 5, lane = tid & 31;
    if (lane == 0) { sh[w] = s; sh[4 + w] = ss; }
    __syncthreads();
    s  = sh[0] + sh[1] + sh[2] + sh[3];
    ss = sh[4] + sh[5] + sh[6] + sh[7];
    float mu  = s * (1.0f / DD);
    float var = ss * (1.0f / DD) - mu * mu;
    float inv = rsqrtf(var + 1e-5f);
    float4 g = reinterpret_cast<const float4*>(gamma)[tid];
    float4 b = reinterpret_cast<const float4*>(beta)[tid];
    float4 o4;
    o4.x = (v.x - mu) * inv * g.x + b.x;
    o4.y = (v.y - mu) * inv * g.y + b.y;
    o4.z = (v.z - mu) * inv * g.z + b.z;
    o4.w = (v.w - mu) * inv * g.w + b.w;
    reinterpret_cast<float4*>(g_xn + (size_t)tok * DD)[tid] = o4;
}

// ------------------------------------------------- tiled SGEMM  C = A @ W^T + bias
// f32x2 packed over the output-j dimension (acc2[i][jp] = C[i][2jp], C[i][2jp+1])
// mode 0: scatter to (B,H,L,dk) layout (QKV projections)
// mode 1: row-major out + residual (output projection)
__global__ __launch_bounds__(256) void gemm_kernel(const float* __restrict__ A,
                                                   const float* __restrict__ W,
                                                   const float* __restrict__ bias,
                                                   float* __restrict__ Cout,
                                                   const float* __restrict__ res,
                                                   int mode)
{
    __shared__ __align__(16) float As[16][68];
    __shared__ __align__(16) float Bs[16][68];
    int tid = threadIdx.x;
    int tx = tid & 15, ty = tid >> 4;
    int m0 = blockIdx.y << 6;
    int n0 = blockIdx.x << 6;
    u64 acc2[4][2] = {};

    for (int k0 = 0; k0 < DD; k0 += 16) {
#pragma unroll
        for (int i = 0; i < 4; i++) {
            int idx = tid + (i << 8);
            int r = idx >> 4, kk = idx & 15;
            As[kk][r] = A[(size_t)(m0 + r) * DD + k0 + kk];
            Bs[kk][r] = W[(size_t)(n0 + r) * DD + k0 + kk];
        }
        __syncthreads();
#pragma unroll
        for (int kk = 0; kk < 16; kk++) {
            float4 a4 = *reinterpret_cast<const float4*>(&As[kk][ty << 2]);
            ulonglong2 b2 = *reinterpret_cast<const ulonglong2*>(&Bs[kk][tx << 2]);
            u64 av[4] = {pack2(a4.x, a4.x), pack2(a4.y, a4.y),
                         pack2(a4.z, a4.z), pack2(a4.w, a4.w)};
#pragma unroll
            for (int i = 0; i < 4; i++) {
                ffma2(acc2[i][0], av[i], b2.x);
                ffma2(acc2[i][1], av[i], b2.y);
            }
        }
        __syncthreads();
    }

    float4 bb4 = *reinterpret_cast<const float4*>(&bias[n0 + (tx << 2)]);
#pragma unroll
    for (int i = 0; i < 4; i++) {
        int mg = m0 + (ty << 2) + i;
        float2 c0 = unpack2(acc2[i][0]);
        float2 c1 = unpack2(acc2[i][1]);
        float4 o4 = make_float4(c0.x + bb4.x, c0.y + bb4.y, c1.x + bb4.z, c1.y + bb4.w);
        if (mode == 0) {
            int bidx = mg / LL, l = mg - bidx * LL;
            int o0 = n0 + (tx << 2);       // h = o0>>6 constant within the quad
            int h = o0 >> 6, dd = o0 & 63;
            *reinterpret_cast<float4*>(
                &Cout[(size_t)bidx * (LL * DD) + (size_t)h * (LL * DKK) +
                      (size_t)l * DKK + dd]) = o4;
        } else {
            size_t off = (size_t)mg * DD + n0 + (tx << 2);
            float4 r4 = *reinterpret_cast<const float4*>(&res[off]);
            o4.x += r4.x; o4.y += r4.y; o4.z += r4.z; o4.w += r4.w;
            *reinterpret_cast<float4*>(&Cout[off]) = o4;
        }
    }
}

// --------------------------------------------------------- flash attention
// per block: 64 query rows of one (b,h); loop over 16 key tiles of 64.
// S = scale * Q@K^T + gather(R),  R = Q @ Rel_band^T (127-wide Toeplitz band)
// all inner GEMMs use FFMA2 packed over the output-column dimension
#define ATTN_SMEM_FLOATS (3*64*68 + 64*132)

__global__ __launch_bounds__(256, 2) void attn_kernel(const float* __restrict__ rel)
{
    extern __shared__ __align__(16) float smf[];
    float* sQt  = smf;              // [64 d][68]  Q^T
    float* sKP  = smf + 64*68;      // [64 d][68]  K^T, later P^T [64 jj][68]
    float* sV   = smf + 2*64*68;    // [64 jj][68] V
    float* sRel = smf + 3*64*68;    // [64 d][132] Rel^T, later R [64 r][132]

    const int tid = threadIdx.x;
    const int tx = tid & 15, ty = tid >> 4;
    const int bh = blockIdx.y;
    const int i0 = blockIdx.x << 6;
    const float* qb = g_q + (size_t)bh * LL * DKK;
    const float* kb = g_k + (size_t)bh * LL * DKK;
    const float* vb = g_v + (size_t)bh * LL * DKK;

    // load Q tile transposed (zero-fill rows >= L)
#pragma unroll
    for (int it = 0; it < 4; it++) {
        int f = tid + (it << 8);
        int r = f >> 4;
        int d4 = (f & 15) << 2;
        int rg = i0 + r;
        float4 qv = make_float4(0.f, 0.f, 0.f, 0.f);
        if (rg < LL) qv = *reinterpret_cast<const float4*>(qb + (size_t)rg * DKK + d4);
        sQt[(d4 + 0) * 68 + r] = qv.x;
        sQt[(d4 + 1) * 68 + r] = qv.y;
        sQt[(d4 + 2) * 68 + r] = qv.z;
        sQt[(d4 + 3) * 68 + r] = qv.w;
    }

    u64 oacc2[4][2] = {};
    float mrow[4] = {-1e30f, -1e30f, -1e30f, -1e30f};
    float lrow[4] = {};
    const float scale = 0.125f;  // 1/sqrt(64)

    for (int j0 = 0; j0 < LL; j0 += 64) {
        __syncthreads();  // protect sKP/sV/sRel from previous iteration readers
        // K^T and V tiles
#pragma unroll
        for (int it = 0; it < 4; it++) {
            int f = tid + (it << 8);
            int r = f >> 4;
            int d4 = (f & 15) << 2;
            int jg = j0 + r;
            float4 kv = make_float4(0.f, 0.f, 0.f, 0.f);
            float4 vv = make_float4(0.f, 0.f, 0.f, 0.f);
            if (jg < LL) {
                kv = *reinterpret_cast<const float4*>(kb + (size_t)jg * DKK + d4);
                vv = *reinterpret_cast<const float4*>(vb + (size_t)jg * DKK + d4);
            }
            sKP[(d4 + 0) * 68 + r] = kv.x;
            sKP[(d4 + 1) * 68 + r] = kv.y;
            sKP[(d4 + 2) * 68 + r] = kv.z;
            sKP[(d4 + 3) * 68 + r] = kv.w;
            *reinterpret_cast<float4*>(&sV[r * 68 + d4]) = vv;
        }
        // rel band: 128 rows starting at mbase (zero-fill out of range)
        int mbase = j0 - i0 + (LL - 1) - 63;
#pragma unroll
        for (int it = 0; it < 8; it++) {
            int f = tid + (it << 8);
            int r = f >> 4;            // 0..127
            int d4 = (f & 15) << 2;
            int mg = mbase + r;
            float4 rv = make_float4(0.f, 0.f, 0.f, 0.f);
            if (mg >= 0 && mg < RELN)
                rv = *reinterpret_cast<const float4*>(rel + (size_t)mg * DKK + d4);
            sRel[(d4 + 0) * 132 + r] = rv.x;
            sRel[(d4 + 1) * 132 + r] = rv.y;
            sRel[(d4 + 2) * 132 + r] = rv.z;
            sRel[(d4 + 3) * 132 + r] = rv.w;
        }
        __syncthreads();

        // fused GEMMs: S_qk (64x64) and R band (64x128), shared A-fragment.
        // sqk2[i][jp] packs columns (2jp, 2jp+1); rr2[i][jp] likewise over 8 cols.
        u64 sqk2[4][2] = {};
        u64 rr2[4][4] = {};
#pragma unroll 4
        for (int d = 0; d < 64; d++) {
            float4 a4 = *reinterpret_cast<const float4*>(&sQt[d * 68 + (ty << 2)]);
            ulonglong2 k2 = *reinterpret_cast<const ulonglong2*>(&sKP[d * 68 + (tx << 2)]);
            ulonglong2 r20 = *reinterpret_cast<const ulonglong2*>(&sRel[d * 132 + (tx << 3)]);
            ulonglong2 r21 = *reinterpret_cast<const ulonglong2*>(&sRel[d * 132 + (tx << 3) + 4]);
            u64 av[4] = {pack2(a4.x, a4.x), pack2(a4.y, a4.y),
                         pack2(a4.z, a4.z), pack2(a4.w, a4.w)};
#pragma unroll
            for (int i = 0; i < 4; i++) {
                ffma2(sqk2[i][0], av[i], k2.x);
                ffma2(sqk2[i][1], av[i], k2.y);
                ffma2(rr2[i][0], av[i], r20.x);
                ffma2(rr2[i][1], av[i], r20.y);
                ffma2(rr2[i][2], av[i], r21.x);
                ffma2(rr2[i][3], av[i], r21.y);
            }
        }
        __syncthreads();
        // write R over the rel buffer (row-major, float2 per packed pair)
#pragma unroll
        for (int i = 0; i < 4; i++)
#pragma unroll
            for (int jp = 0; jp < 4; jp++) {
                float2 rpair = unpack2(rr2[i][jp]);
                *reinterpret_cast<float2*>(
                    &sRel[((ty << 2) + i) * 132 + (tx << 3) + (jp << 1)]) = rpair;
            }
        __syncthreads();

        // gather + online softmax (rows ty*4+i; 16 lanes of same ty share a row)
        float p[4][4];
#pragma unroll
        for (int i = 0; i < 4; i++) {
            int row = (ty << 2) + i;
            float2 q0 = unpack2(sqk2[i][0]);
            float2 q1 = unpack2(sqk2[i][1]);
            float sv4[4] = {q0.x, q0.y, q1.x, q1.y};
            float mx = -1e30f;
#pragma unroll
            for (int j = 0; j < 4; j++) {
                int col = (tx << 2) + j;
                float sc = sv4[j] * scale + sRel[row * 132 + (col - row + 63)];
                if (j0 + col >= LL) sc = -1e30f;
                p[i][j] = sc;
                mx = fmaxf(mx, sc);
            }
#pragma unroll
            for (int o = 1; o < 16; o <<= 1)
                mx = fmaxf(mx, __shfl_xor_sync(0xffffffffu, mx, o));
            float mnew = fmaxf(mrow[i], mx);
            float corr = __expf(mrow[i] - mnew);
            mrow[i] = mnew;
            float ls = 0.f;
#pragma unroll
            for (int j = 0; j < 4; j++) {
                p[i][j] = __expf(p[i][j] - mnew);
                ls += p[i][j];
            }
#pragma unroll
            for (int o = 1; o < 16; o <<= 1)
                ls += __shfl_xor_sync(0xffffffffu, ls, o);
            lrow[i] = lrow[i] * corr + ls;
            u64 c2 = pack2(corr, corr);
            fmul2(oacc2[i][0], c2);
            fmul2(oacc2[i][1], c2);
        }
        // P^T into sKP (K tile fully consumed)
#pragma unroll
        for (int i = 0; i < 4; i++)
#pragma unroll
            for (int j = 0; j < 4; j++)
                sKP[((tx << 2) + j) * 68 + (ty << 2) + i] = p[i][j];
        __syncthreads();

        // O += P @ V  (packed over output d-pairs)
#pragma unroll 8
        for (int jj = 0; jj < 64; jj++) {
            float4 pa = *reinterpret_cast<const float4*>(&sKP[jj * 68 + (ty << 2)]);
            ulonglong2 v2 = *reinterpret_cast<const ulonglong2*>(&sV[jj * 68 + (tx << 2)]);
            u64 pv[4] = {pack2(pa.x, pa.x), pack2(pa.y, pa.y),
                         pack2(pa.z, pa.z), pack2(pa.w, pa.w)};
#pragma unroll
            for (int i = 0; i < 4; i++) {
                ffma2(oacc2[i][0], pv[i], v2.x);
                ffma2(oacc2[i][1], pv[i], v2.y);
            }
        }
    }

    // epilogue: normalize and scatter to (B,L,D)
    int b = bh >> 3, h = bh & 7;
#pragma unroll
    for (int i = 0; i < 4; i++) {
        int rg = i0 + (ty << 2) + i;
        if (rg < LL) {
            float invl = 1.0f / lrow[i];
            float2 c0 = unpack2(oacc2[i][0]);
            float2 c1 = unpack2(oacc2[i][1]);
            float4 o4 = make_float4(c0.x * invl, c0.y * invl, c1.x * invl, c1.y * invl);
            *reinterpret_cast<float4*>(
                &g_ctx[((size_t)b * LL + rg) * DD + h * 64 + (tx << 2)]) = o4;
        }
    }
}

// ---------------------------------------------------------------- launcher
extern "C" void kernel_launch(void* const* d_in, const int* in_sizes, int n_in,
                              void* d_out, int out_size)
{
    const float* x     = (const float*)d_in[0];
    const float* Wq    = (const float*)d_in[1];
    const float* bq    = (const float*)d_in[2];
    const float* Wk    = (const float*)d_in[3];
    const float* bk    = (const float*)d_in[4];
    const float* Wv    = (const float*)d_in[5];
    const float* bv    = (const float*)d_in[6];
    const float* Wo    = (const float*)d_in[7];
    const float* bo    = (const float*)d_in[8];
    const float* rel   = (const float*)d_in[9];
    const float* gamma = (const float*)d_in[10];
    const float* beta  = (const float*)d_in[11];
    float* out = (float*)d_out;

    float *xn, *q, *k, *v, *ctx;
    cudaGetSymbolAddress((void**)&xn,  g_xn);
    cudaGetSymbolAddress((void**)&q,   g_q);
    cudaGetSymbolAddress((void**)&k,   g_k);
    cudaGetSymbolAddress((void**)&v,   g_v);
    cudaGetSymbolAddress((void**)&ctx, g_ctx);

    cudaFuncSetAttribute(attn_kernel, cudaFuncAttributeMaxDynamicSharedMemorySize,
                         ATTN_SMEM_FLOATS * (int)sizeof(float));

    ln_kernel<<<NTOK, 128>>>(x, gamma, beta);

    dim3 gg(DD / 64, NTOK / 64);  // (8, 125)
    gemm_kernel<<<gg, 256>>>(xn, Wq, bq, q, nullptr, 0);
    gemm_kernel<<<gg, 256>>>(xn, Wk, bk, k, nullptr, 0);
    gemm_kernel<<<gg, 256>>>(xn, Wv, bv, v, nullptr, 0);

    dim3 ga((LL + 63) / 64, BB * HH);  // (16, 64)
    attn_kernel<<<ga, 256, ATTN_SMEM_FLOATS * sizeof(float)>>>(rel);

    gemm_kernel<<<gg, 256>>>(ctx, Wo, bo, out, x, 1);
}

// round 3
// speedup vs baseline: 1.1719x; 1.1719x over previous
#include <cuda_runtime.h>
#include <cuda_bf16.h>
#include <math.h>

#define BB 8
#define LL 1000
#define DD 512
#define HH 8
#define DKK 64
#define NTOK (BB*LL)
#define RELN (2*LL-1)

typedef unsigned int u32;

// ------------------------------------------------------------ scratch
__device__ float g_q[NTOK*DD];   // (B,H,L,dk)
__device__ float g_k[NTOK*DD];
__device__ float g_v[NTOK*DD];
__device__ float g_ctx[NTOK*DD]; // (B,L,D)
__device__ __nv_bfloat16 g_xnh[NTOK*DD];
__device__ __nv_bfloat16 g_xnl[NTOK*DD];
__device__ __nv_bfloat16 g_cth[NTOK*DD];
__device__ __nv_bfloat16 g_ctl[NTOK*DD];
__device__ __nv_bfloat16 g_wh[4*DD*DD];
__device__ __nv_bfloat16 g_wl[4*DD*DD];

// ------------------------------------------------------------ mma helpers
__device__ __forceinline__ void mma16816(float* d, const u32* a, const u32* b) {
    asm volatile(
        "mma.sync.aligned.m16n8k16.row.col.f32.bf16.bf16.f32 "
        "{%0,%1,%2,%3}, {%4,%5,%6,%7}, {%8,%9}, {%0,%1,%2,%3};"
        : "+f"(d[0]), "+f"(d[1]), "+f"(d[2]), "+f"(d[3])
        : "r"(a[0]), "r"(a[1]), "r"(a[2]), "r"(a[3]), "r"(b[0]), "r"(b[1]));
}
__device__ __forceinline__ void ldsm4(u32* r, u32 addr) {
    asm volatile("ldmatrix.sync.aligned.m8n8.x4.shared.b16 {%0,%1,%2,%3}, [%4];"
                 : "=r"(r[0]), "=r"(r[1]), "=r"(r[2]), "=r"(r[3]) : "r"(addr));
}

// ------------------------------------------------------------ LayerNorm + bf16 split
__global__ __launch_bounds__(128) void ln_kernel(const float* __restrict__ x,
                                                 const float* __restrict__ gamma,
                                                 const float* __restrict__ beta)
{
    int tok = blockIdx.x;
    int tid = threadIdx.x;
    const float4 v = reinterpret_cast<const float4*>(x + (size_t)tok * DD)[tid];
    float s  = v.x + v.y + v.z + v.w;
    float ss = v.x*v.x + v.y*v.y + v.z*v.z + v.w*v.w;
#pragma unroll
    for (int o = 16; o; o >>= 1) {
        s  += __shfl_xor_sync(0xffffffffu, s,  o);
        ss += __shfl_xor_sync(0xffffffffu, ss, o);
    }
    __shared__ float sh[8];
    int w = tid >> 5, lane = tid & 31;
    if (lane == 0) { sh[w] = s; sh[4 + w] = ss; }
    __syncthreads();
    s  = sh[0] + sh[1] + sh[2] + sh[3];
    ss = sh[4] + sh[5] + sh[6] + sh[7];
    float mu  = s * (1.0f / DD);
    float var = ss * (1.0f / DD) - mu * mu;
    float inv = rsqrtf(var + 1e-5f);
    float4 g = reinterpret_cast<const float4*>(gamma)[tid];
    float4 b = reinterpret_cast<const float4*>(beta)[tid];
    float o0 = (v.x - mu) * inv * g.x + b.x;
    float o1 = (v.y - mu) * inv * g.y + b.y;
    float o2 = (v.z - mu) * inv * g.z + b.z;
    float o3 = (v.w - mu) * inv * g.w + b.w;
    __nv_bfloat16 h0 = __float2bfloat16_rn(o0), h1 = __float2bfloat16_rn(o1);
    __nv_bfloat16 h2 = __float2bfloat16_rn(o2), h3 = __float2bfloat16_rn(o3);
    __nv_bfloat16 l0 = __float2bfloat16_rn(o0 - __bfloat162float(h0));
    __nv_bfloat16 l1 = __float2bfloat16_rn(o1 - __bfloat162float(h1));
    __nv_bfloat16 l2 = __float2bfloat16_rn(o2 - __bfloat162float(h2));
    __nv_bfloat16 l3 = __float2bfloat16_rn(o3 - __bfloat162float(h3));
    size_t base = (size_t)tok * DD + tid * 4;
    *reinterpret_cast<__nv_bfloat162*>(&g_xnh[base])     = __halves2bfloat162(h0, h1);
    *reinterpret_cast<__nv_bfloat162*>(&g_xnh[base + 2]) = __halves2bfloat162(h2, h3);
    *reinterpret_cast<__nv_bfloat162*>(&g_xnl[base])     = __halves2bfloat162(l0, l1);
    *reinterpret_cast<__nv_bfloat162*>(&g_xnl[base + 2]) = __halves2bfloat162(l2, l3);
}

// ------------------------------------------------------------ fp32 -> bf16 hi/lo split
__global__ __launch_bounds__(256) void split_kernel(const float* __restrict__ src,
                                                    __nv_bfloat16* __restrict__ hi,
                                                    __nv_bfloat16* __restrict__ lo)
{
    size_t i = ((size_t)blockIdx.x * blockDim.x + threadIdx.x) * 4;
    float4 v = *reinterpret_cast<const float4*>(src + i);
    __nv_bfloat16 h0 = __float2bfloat16_rn(v.x), h1 = __float2bfloat16_rn(v.y);
    __nv_bfloat16 h2 = __float2bfloat16_rn(v.z), h3 = __float2bfloat16_rn(v.w);
    __nv_bfloat16 l0 = __float2bfloat16_rn(v.x - __bfloat162float(h0));
    __nv_bfloat16 l1 = __float2bfloat16_rn(v.y - __bfloat162float(h1));
    __nv_bfloat16 l2 = __float2bfloat16_rn(v.z - __bfloat162float(h2));
    __nv_bfloat16 l3 = __float2bfloat16_rn(v.w - __bfloat162float(h3));
    *reinterpret_cast<__nv_bfloat162*>(&hi[i])     = __halves2bfloat162(h0, h1);
    *reinterpret_cast<__nv_bfloat162*>(&hi[i + 2]) = __halves2bfloat162(h2, h3);
    *reinterpret_cast<__nv_bfloat162*>(&lo[i])     = __halves2bfloat162(l0, l1);
    *reinterpret_cast<__nv_bfloat162*>(&lo[i + 2]) = __halves2bfloat162(l2, l3);
}

// ------------------------------------------------------------ tensor-core GEMM
// C(M=8000, N=512) = A @ W^T + bias, bf16-split (Ah·Wh + Ah·Wl + Al·Wh), fp32 acc.
// block tile 128x64, 8 warps (4m x 2n), warp tile 32x32, BK=32.
// mode 0: scatter to (B,H,L,dk); mode 1: row-major + residual.
#define GSTRIDE 40  // smem row stride in bf16 elems (80B: 16B-aligned, LDSM conflict-free)

__global__ __launch_bounds__(256, 2) void gemm_tc_kernel(
    const __nv_bfloat16* __restrict__ Ah, const __nv_bfloat16* __restrict__ Al,
    const __nv_bfloat16* __restrict__ Wh, const __nv_bfloat16* __restrict__ Wl,
    const float* __restrict__ bias, float* __restrict__ Cout,
    const float* __restrict__ res, int mode)
{
    __shared__ __align__(16) __nv_bfloat16 sAh[128 * GSTRIDE];
    __shared__ __align__(16) __nv_bfloat16 sAl[128 * GSTRIDE];
    __shared__ __align__(16) __nv_bfloat16 sBh[64 * GSTRIDE];
    __shared__ __align__(16) __nv_bfloat16 sBl[64 * GSTRIDE];

    const int tid = threadIdx.x;
    const int lane = tid & 31, wid = tid >> 5;
    const int wm = wid & 3, wn = wid >> 2;      // warp grid 4 x 2
    const int m0 = blockIdx.y * 128;
    const int n0 = blockIdx.x * 64;

    const u32 uAh = (u32)__cvta_generic_to_shared(sAh);
    const u32 uAl = (u32)__cvta_generic_to_shared(sAl);
    const u32 uBh = (u32)__cvta_generic_to_shared(sBh);
    const u32 uBl = (u32)__cvta_generic_to_shared(sBl);

    float acc[2][4][4] = {};

    const int lrow = tid >> 2;            // 0..63
    const int lcol = (tid & 3) << 3;      // 0,8,16,24

    for (int k0 = 0; k0 < DD; k0 += 32) {
        // global -> smem (A: 128 rows in 2 iters; B: 64 rows in 1)
#pragma unroll
        for (int it = 0; it < 2; it++) {
            int r = lrow + it * 64;
            int mg = m0 + r;
            uint4 vh = make_uint4(0, 0, 0, 0), vl = make_uint4(0, 0, 0, 0);
            if (mg < NTOK) {
                vh = *reinterpret_cast<const uint4*>(&Ah[(size_t)mg * DD + k0 + lcol]);
                vl = *reinterpret_cast<const uint4*>(&Al[(size_t)mg * DD + k0 + lcol]);
            }
            *reinterpret_cast<uint4*>(&sAh[r * GSTRIDE + lcol]) = vh;
            *reinterpret_cast<uint4*>(&sAl[r * GSTRIDE + lcol]) = vl;
        }
        {
            int ng = n0 + lrow;
            uint4 vh = *reinterpret_cast<const uint4*>(&Wh[(size_t)ng * DD + k0 + lcol]);
            uint4 vl = *reinterpret_cast<const uint4*>(&Wl[(size_t)ng * DD + k0 + lcol]);
            *reinterpret_cast<uint4*>(&sBh[lrow * GSTRIDE + lcol]) = vh;
            *reinterpret_cast<uint4*>(&sBl[lrow * GSTRIDE + lcol]) = vl;
        }
        __syncthreads();

#pragma unroll
        for (int kt = 0; kt < 32; kt += 16) {
            u32 afh[2][4], afl[2][4], bfh[8], bfl[8];
            // A fragments (two 16-row tiles)
#pragma unroll
            for (int mt = 0; mt < 2; mt++) {
                int row = wm * 32 + mt * 16 + (lane & 7) + ((lane >> 3) & 1) * 8;
                int col = kt + (lane >> 4) * 8;
                u32 off = (u32)(row * GSTRIDE + col) * 2;
                ldsm4(afh[mt], uAh + off);
                ldsm4(afl[mt], uAl + off);
            }
            // B fragments (four 8-col tiles, two x4 loads per plane)
            {
                int g = lane >> 3, r = lane & 7;
                int row = wn * 32 + ((g >> 1) & 1) * 8 + r;
                int col = kt + (g & 1) * 8;
                u32 off = (u32)(row * GSTRIDE + col) * 2;
                u32 off2 = off + 16 * GSTRIDE * 2;
                ldsm4(&bfh[0], uBh + off);
                ldsm4(&bfl[0], uBl + off);
                ldsm4(&bfh[4], uBh + off2);
                ldsm4(&bfl[4], uBl + off2);
            }
#pragma unroll
            for (int mt = 0; mt < 2; mt++)
#pragma unroll
                for (int nt = 0; nt < 4; nt++) {
                    mma16816(acc[mt][nt], afh[mt], &bfh[nt * 2]);
                    mma16816(acc[mt][nt], afh[mt], &bfl[nt * 2]);
                    mma16816(acc[mt][nt], afl[mt], &bfh[nt * 2]);
                }
        }
        __syncthreads();
    }

    // epilogue
    const int r = lane >> 2, c = (lane & 3) << 1;
#pragma unroll
    for (int mt = 0; mt < 2; mt++) {
#pragma unroll
        for (int nt = 0; nt < 4; nt++) {
            int n = n0 + wn * 32 + nt * 8 + c;
            float b0 = bias[n], b1 = bias[n + 1];
#pragma unroll
            for (int half = 0; half < 2; half++) {
                int m = m0 + wm * 32 + mt * 16 + r + half * 8;
                if (m >= NTOK) continue;
                float2 o2 = make_float2(acc[mt][nt][half * 2] + b0,
                                        acc[mt][nt][half * 2 + 1] + b1);
                if (mode == 0) {
                    int bidx = m / LL, l = m - bidx * LL;
                    int h = n >> 6, dd = n & 63;
                    *reinterpret_cast<float2*>(
                        &Cout[(size_t)bidx * (LL * DD) + (size_t)h * (LL * DKK) +
                              (size_t)l * DKK + dd]) = o2;
                } else {
                    size_t off = (size_t)m * DD + n;
                    float2 r2 = *reinterpret_cast<const float2*>(&res[off]);
                    o2.x += r2.x; o2.y += r2.y;
                    *reinterpret_cast<float2*>(&Cout[off]) = o2;
                }
            }
        }
    }
}

// --------------------------------------------------------- flash attention (scalar, R1)
#define ATTN_SMEM_FLOATS (3*64*68 + 64*132)

__global__ __launch_bounds__(256, 2) void attn_kernel(const float* __restrict__ rel)
{
    extern __shared__ float smf[];
    float* sQt  = smf;              // [64 d][68]  Q^T
    float* sKP  = smf + 64*68;      // [64 d][68]  K^T, later P^T [64 jj][68]
    float* sV   = smf + 2*64*68;    // [64 jj][68] V
    float* sRel = smf + 3*64*68;    // [64 d][132] Rel^T, later R [64 r][132]

    const int tid = threadIdx.x;
    const int tx = tid & 15, ty = tid >> 4;
    const int bh = blockIdx.y;
    const int i0 = blockIdx.x << 6;
    const float* qb = g_q + (size_t)bh * LL * DKK;
    const float* kb = g_k + (size_t)bh * LL * DKK;
    const float* vb = g_v + (size_t)bh * LL * DKK;

#pragma unroll
    for (int it = 0; it < 4; it++) {
        int f = tid + (it << 8);
        int r = f >> 4;
        int d4 = (f & 15) << 2;
        int rg = i0 + r;
        float4 qv = make_float4(0.f, 0.f, 0.f, 0.f);
        if (rg < LL) qv = *reinterpret_cast<const float4*>(qb + (size_t)rg * DKK + d4);
        sQt[(d4 + 0) * 68 + r] = qv.x;
        sQt[(d4 + 1) * 68 + r] = qv.y;
        sQt[(d4 + 2) * 68 + r] = qv.z;
        sQt[(d4 + 3) * 68 + r] = qv.w;
    }

    float oacc[4][4] = {};
    float mrow[4] = {-1e30f, -1e30f, -1e30f, -1e30f};
    float lrow[4] = {};
    const float scale = 0.125f;

    for (int j0 = 0; j0 < LL; j0 += 64) {
        __syncthreads();
#pragma unroll
        for (int it = 0; it < 4; it++) {
            int f = tid + (it << 8);
            int r = f >> 4;
            int d4 = (f & 15) << 2;
            int jg = j0 + r;
            float4 kv = make_float4(0.f, 0.f, 0.f, 0.f);
            float4 vv = make_float4(0.f, 0.f, 0.f, 0.f);
            if (jg < LL) {
                kv = *reinterpret_cast<const float4*>(kb + (size_t)jg * DKK + d4);
                vv = *reinterpret_cast<const float4*>(vb + (size_t)jg * DKK + d4);
            }
            sKP[(d4 + 0) * 68 + r] = kv.x;
            sKP[(d4 + 1) * 68 + r] = kv.y;
            sKP[(d4 + 2) * 68 + r] = kv.z;
            sKP[(d4 + 3) * 68 + r] = kv.w;
            *reinterpret_cast<float4*>(&sV[r * 68 + d4]) = vv;
        }
        int mbase = j0 - i0 + (LL - 1) - 63;
#pragma unroll
        for (int it = 0; it < 8; it++) {
            int f = tid + (it << 8);
            int r = f >> 4;
            int d4 = (f & 15) << 2;
            int mg = mbase + r;
            float4 rv = make_float4(0.f, 0.f, 0.f, 0.f);
            if (mg >= 0 && mg < RELN)
                rv = *reinterpret_cast<const float4*>(rel + (size_t)mg * DKK + d4);
            sRel[(d4 + 0) * 132 + r] = rv.x;
            sRel[(d4 + 1) * 132 + r] = rv.y;
            sRel[(d4 + 2) * 132 + r] = rv.z;
            sRel[(d4 + 3) * 132 + r] = rv.w;
        }
        __syncthreads();

        float sqk[4][4] = {};
        float rr[4][8] = {};
#pragma unroll 8
        for (int d = 0; d < 64; d++) {
            float4 a4 = *reinterpret_cast<const float4*>(&sQt[d * 68 + (ty << 2)]);
            float4 k4 = *reinterpret_cast<const float4*>(&sKP[d * 68 + (tx << 2)]);
            float4 r0 = *reinterpret_cast<const float4*>(&sRel[d * 132 + (tx << 3)]);
            float4 r1 = *reinterpret_cast<const float4*>(&sRel[d * 132 + (tx << 3) + 4]);
            float av[4] = {a4.x, a4.y, a4.z, a4.w};
            float kv[4] = {k4.x, k4.y, k4.z, k4.w};
            float rv[8] = {r0.x, r0.y, r0.z, r0.w, r1.x, r1.y, r1.z, r1.w};
#pragma unroll
            for (int i = 0; i < 4; i++) {
#pragma unroll
                for (int j = 0; j < 4; j++) sqk[i][j] += av[i] * kv[j];
#pragma unroll
                for (int j = 0; j < 8; j++) rr[i][j] += av[i] * rv[j];
            }
        }
        __syncthreads();
#pragma unroll
        for (int i = 0; i < 4; i++)
#pragma unroll
            for (int j = 0; j < 8; j++)
                sRel[((ty << 2) + i) * 132 + (tx << 3) + j] = rr[i][j];
        __syncthreads();

        float p[4][4];
#pragma unroll
        for (int i = 0; i < 4; i++) {
            int row = (ty << 2) + i;
            float mx = -1e30f;
#pragma unroll
            for (int j = 0; j < 4; j++) {
                int col = (tx << 2) + j;
                float sc = sqk[i][j] * scale + sRel[row * 132 + (col - row + 63)];
                if (j0 + col >= LL) sc = -1e30f;
                p[i][j] = sc;
                mx = fmaxf(mx, sc);
            }
#pragma unroll
            for (int o = 1; o < 16; o <<= 1)
                mx = fmaxf(mx, __shfl_xor_sync(0xffffffffu, mx, o));
            float mnew = fmaxf(mrow[i], mx);
            float corr = __expf(mrow[i] - mnew);
            mrow[i] = mnew;
            float ls = 0.f;
#pragma unroll
            for (int j = 0; j < 4; j++) {
                p[i][j] = __expf(p[i][j] - mnew);
                ls += p[i][j];
            }
#pragma unroll
            for (int o = 1; o < 16; o <<= 1)
                ls += __shfl_xor_sync(0xffffffffu, ls, o);
            lrow[i] = lrow[i] * corr + ls;
#pragma unroll
            for (int j = 0; j < 4; j++) oacc[i][j] *= corr;
        }
#pragma unroll
        for (int i = 0; i < 4; i++)
#pragma unroll
            for (int j = 0; j < 4; j++)
                sKP[((tx << 2) + j) * 68 + (ty << 2) + i] = p[i][j];
        __syncthreads();

#pragma unroll 8
        for (int jj = 0; jj < 64; jj++) {
            float4 pa = *reinterpret_cast<const float4*>(&sKP[jj * 68 + (ty << 2)]);
            float4 v4 = *reinterpret_cast<const float4*>(&sV[jj * 68 + (tx << 2)]);
            float pv[4] = {pa.x, pa.y, pa.z, pa.w};
            float vv[4] = {v4.x, v4.y, v4.z, v4.w};
#pragma unroll
            for (int i = 0; i < 4; i++)
#pragma unroll
                for (int j = 0; j < 4; j++)
                    oacc[i][j] += pv[i] * vv[j];
        }
    }

    int b = bh >> 3, h = bh & 7;
#pragma unroll
    for (int i = 0; i < 4; i++) {
        int rg = i0 + (ty << 2) + i;
        if (rg < LL) {
            float invl = 1.0f / lrow[i];
            float4 o4 = make_float4(oacc[i][0] * invl, oacc[i][1] * invl,
                                    oacc[i][2] * invl, oacc[i][3] * invl);
            *reinterpret_cast<float4*>(
                &g_ctx[((size_t)b * LL + rg) * DD + h * 64 + (tx << 2)]) = o4;
        }
    }
}

// ---------------------------------------------------------------- launcher
extern "C" void kernel_launch(void* const* d_in, const int* in_sizes, int n_in,
                              void* d_out, int out_size)
{
    const float* x     = (const float*)d_in[0];
    const float* Wq    = (const float*)d_in[1];
    const float* bq    = (const float*)d_in[2];
    const float* Wk    = (const float*)d_in[3];
    const float* bk    = (const float*)d_in[4];
    const float* Wv    = (const float*)d_in[5];
    const float* bv    = (const float*)d_in[6];
    const float* Wo    = (const float*)d_in[7];
    const float* bo    = (const float*)d_in[8];
    const float* rel   = (const float*)d_in[9];
    const float* gamma = (const float*)d_in[10];
    const float* beta  = (const float*)d_in[11];
    float* out = (float*)d_out;

    float *q, *k, *v, *ctx;
    __nv_bfloat16 *xnh, *xnl, *cth, *ctl, *wh, *wl;
    cudaGetSymbolAddress((void**)&q,   g_q);
    cudaGetSymbolAddress((void**)&k,   g_k);
    cudaGetSymbolAddress((void**)&v,   g_v);
    cudaGetSymbolAddress((void**)&ctx, g_ctx);
    cudaGetSymbolAddress((void**)&xnh, g_xnh);
    cudaGetSymbolAddress((void**)&xnl, g_xnl);
    cudaGetSymbolAddress((void**)&cth, g_cth);
    cudaGetSymbolAddress((void**)&ctl, g_ctl);
    cudaGetSymbolAddress((void**)&wh,  g_wh);
    cudaGetSymbolAddress((void**)&wl,  g_wl);

    cudaFuncSetAttribute(attn_kernel, cudaFuncAttributeMaxDynamicSharedMemorySize,
                         ATTN_SMEM_FLOATS * (int)sizeof(float));

    // LayerNorm -> split planes; weight splits
    ln_kernel<<<NTOK, 128>>>(x, gamma, beta);
    split_kernel<<<DD*DD/1024, 256>>>(Wq, wh + 0*DD*DD, wl + 0*DD*DD);
    split_kernel<<<DD*DD/1024, 256>>>(Wk, wh + 1*DD*DD, wl + 1*DD*DD);
    split_kernel<<<DD*DD/1024, 256>>>(Wv, wh + 2*DD*DD, wl + 2*DD*DD);
    split_kernel<<<DD*DD/1024, 256>>>(Wo, wh + 3*DD*DD, wl + 3*DD*DD);

    dim3 gg(DD / 64, (NTOK + 127) / 128);  // (8, 63)
    gemm_tc_kernel<<<gg, 256>>>(xnh, xnl, wh + 0*DD*DD, wl + 0*DD*DD, bq, q, nullptr, 0);
    gemm_tc_kernel<<<gg, 256>>>(xnh, xnl, wh + 1*DD*DD, wl + 1*DD*DD, bk, k, nullptr, 0);
    gemm_tc_kernel<<<gg, 256>>>(xnh, xnl, wh + 2*DD*DD, wl + 2*DD*DD, bv, v, nullptr, 0);

    dim3 ga((LL + 63) / 64, BB * HH);  // (16, 64)
    attn_kernel<<<ga, 256, ATTN_SMEM_FLOATS * sizeof(float)>>>(rel);

    split_kernel<<<NTOK*DD/1024, 256>>>(ctx, cth, ctl);
    gemm_tc_kernel<<<gg, 256>>>(cth, ctl, wh + 3*DD*DD, wl + 3*DD*DD, bo, out, x, 1);
}

// round 4
// speedup vs baseline: 1.8426x; 1.5724x over previous
#include <cuda_runtime.h>
#include <cuda_bf16.h>
#include <math.h>

#define BB 8
#define LL 1000
#define DD 512
#define HH 8
#define DKK 64
#define NTOK (BB*LL)
#define RELN (2*LL-1)

typedef unsigned int u32;

// ------------------------------------------------------------ scratch (bf16 hi/lo planes)
__device__ __nv_bfloat16 g_xnh[NTOK*DD];
__device__ __nv_bfloat16 g_xnl[NTOK*DD];
__device__ __nv_bfloat16 g_qh[NTOK*DD];  // (B,H,L,dk)
__device__ __nv_bfloat16 g_ql[NTOK*DD];
__device__ __nv_bfloat16 g_kh[NTOK*DD];  // pre-scaled by 1/8
__device__ __nv_bfloat16 g_kl[NTOK*DD];
__device__ __nv_bfloat16 g_vh[NTOK*DD];
__device__ __nv_bfloat16 g_vl[NTOK*DD];
__device__ __nv_bfloat16 g_cth[NTOK*DD]; // ctx (B,L,D)
__device__ __nv_bfloat16 g_ctl[NTOK*DD];
__device__ __nv_bfloat16 g_wh[4*DD*DD];
__device__ __nv_bfloat16 g_wl[4*DD*DD];
__device__ __nv_bfloat16 g_relh[RELN*DKK];
__device__ __nv_bfloat16 g_rell[RELN*DKK];

// ------------------------------------------------------------ mma helpers
__device__ __forceinline__ void mma16816(float* d, const u32* a, const u32* b) {
    asm volatile(
        "mma.sync.aligned.m16n8k16.row.col.f32.bf16.bf16.f32 "
        "{%0,%1,%2,%3}, {%4,%5,%6,%7}, {%8,%9}, {%0,%1,%2,%3};"
        : "+f"(d[0]), "+f"(d[1]), "+f"(d[2]), "+f"(d[3])
        : "r"(a[0]), "r"(a[1]), "r"(a[2]), "r"(a[3]), "r"(b[0]), "r"(b[1]));
}
__device__ __forceinline__ void ldsm4(u32* r, u32 addr) {
    asm volatile("ldmatrix.sync.aligned.m8n8.x4.shared.b16 {%0,%1,%2,%3}, [%4];"
                 : "=r"(r[0]), "=r"(r[1]), "=r"(r[2]), "=r"(r[3]) : "r"(addr));
}
__device__ __forceinline__ void ldsm4t(u32* r, u32 addr) {
    asm volatile("ldmatrix.sync.aligned.m8n8.x4.trans.shared.b16 {%0,%1,%2,%3}, [%4];"
                 : "=r"(r[0]), "=r"(r[1]), "=r"(r[2]), "=r"(r[3]) : "r"(addr));
}
__device__ __forceinline__ void split_store2(__nv_bfloat16* H, __nv_bfloat16* L,
                                             size_t idx, float x, float y) {
    __nv_bfloat16 hx = __float2bfloat16_rn(x), hy = __float2bfloat16_rn(y);
    *reinterpret_cast<__nv_bfloat162*>(&H[idx]) = __halves2bfloat162(hx, hy);
    *reinterpret_cast<__nv_bfloat162*>(&L[idx]) = __halves2bfloat162(
        __float2bfloat16_rn(x - __bfloat162float(hx)),
        __float2bfloat16_rn(y - __bfloat162float(hy)));
}

// ------------------------------------------------------------ LayerNorm + bf16 split
__global__ __launch_bounds__(128) void ln_kernel(const float* __restrict__ x,
                                                 const float* __restrict__ gamma,
                                                 const float* __restrict__ beta)
{
    int tok = blockIdx.x;
    int tid = threadIdx.x;
    const float4 v = reinterpret_cast<const float4*>(x + (size_t)tok * DD)[tid];
    float s  = v.x + v.y + v.z + v.w;
    float ss = v.x*v.x + v.y*v.y + v.z*v.z + v.w*v.w;
#pragma unroll
    for (int o = 16; o; o >>= 1) {
        s  += __shfl_xor_sync(0xffffffffu, s,  o);
        ss += __shfl_xor_sync(0xffffffffu, ss, o);
    }
    __shared__ float sh[8];
    int w = tid >> 5, lane = tid & 31;
    if (lane == 0) { sh[w] = s; sh[4 + w] = ss; }
    __syncthreads();
    s  = sh[0] + sh[1] + sh[2] + sh[3];
    ss = sh[4] + sh[5] + sh[6] + sh[7];
    float mu  = s * (1.0f / DD);
    float var = ss * (1.0f / DD) - mu * mu;
    float inv = rsqrtf(var + 1e-5f);
    float4 g = reinterpret_cast<const float4*>(gamma)[tid];
    float4 b = reinterpret_cast<const float4*>(beta)[tid];
    float o0 = (v.x - mu) * inv * g.x + b.x;
    float o1 = (v.y - mu) * inv * g.y + b.y;
    float o2 = (v.z - mu) * inv * g.z + b.z;
    float o3 = (v.w - mu) * inv * g.w + b.w;
    size_t base = (size_t)tok * DD + tid * 4;
    split_store2(g_xnh, g_xnl, base,     o0, o1);
    split_store2(g_xnh, g_xnl, base + 2, o2, o3);
}

// ------------------------------------------------------------ fp32 -> bf16 hi/lo split
__global__ __launch_bounds__(256) void split_kernel(const float* __restrict__ src,
                                                    __nv_bfloat16* __restrict__ hi,
                                                    __nv_bfloat16* __restrict__ lo,
                                                    int n4)
{
    int iv = blockIdx.x * blockDim.x + threadIdx.x;
    if (iv >= n4) return;
    size_t i = (size_t)iv * 4;
    float4 v = *reinterpret_cast<const float4*>(src + i);
    split_store2(hi, lo, i,     v.x, v.y);
    split_store2(hi, lo, i + 2, v.z, v.w);
}

// ------------------------------------------------------------ tensor-core GEMM
// mode 0: write bf16 hi/lo planes scattered to (B,H,L,dk), scaled.
// mode 1: fp32 row-major out + residual.
#define GSTRIDE 40

__global__ __launch_bounds__(256, 2) void gemm_tc_kernel(
    const __nv_bfloat16* __restrict__ Ah, const __nv_bfloat16* __restrict__ Al,
    const __nv_bfloat16* __restrict__ Wh, const __nv_bfloat16* __restrict__ Wl,
    const float* __restrict__ bias, float* __restrict__ CoutF,
    const float* __restrict__ res,
    __nv_bfloat16* __restrict__ CoutH, __nv_bfloat16* __restrict__ CoutL,
    float scale, int mode)
{
    __shared__ __align__(16) __nv_bfloat16 sAh[128 * GSTRIDE];
    __shared__ __align__(16) __nv_bfloat16 sAl[128 * GSTRIDE];
    __shared__ __align__(16) __nv_bfloat16 sBh[64 * GSTRIDE];
    __shared__ __align__(16) __nv_bfloat16 sBl[64 * GSTRIDE];

    const int tid = threadIdx.x;
    const int lane = tid & 31, wid = tid >> 5;
    const int wm = wid & 3, wn = wid >> 2;
    const int m0 = blockIdx.y * 128;
    const int n0 = blockIdx.x * 64;

    const u32 uAh = (u32)__cvta_generic_to_shared(sAh);
    const u32 uAl = (u32)__cvta_generic_to_shared(sAl);
    const u32 uBh = (u32)__cvta_generic_to_shared(sBh);
    const u32 uBl = (u32)__cvta_generic_to_shared(sBl);

    float acc[2][4][4] = {};

    const int lrow = tid >> 2;
    const int lcol = (tid & 3) << 3;

    for (int k0 = 0; k0 < DD; k0 += 32) {
#pragma unroll
        for (int it = 0; it < 2; it++) {
            int r = lrow + it * 64;
            int mg = m0 + r;
            uint4 vh = make_uint4(0, 0, 0, 0), vl = make_uint4(0, 0, 0, 0);
            if (mg < NTOK) {
                vh = *reinterpret_cast<const uint4*>(&Ah[(size_t)mg * DD + k0 + lcol]);
                vl = *reinterpret_cast<const uint4*>(&Al[(size_t)mg * DD + k0 + lcol]);
            }
            *reinterpret_cast<uint4*>(&sAh[r * GSTRIDE + lcol]) = vh;
            *reinterpret_cast<uint4*>(&sAl[r * GSTRIDE + lcol]) = vl;
        }
        {
            int ng = n0 + lrow;
            uint4 vh = *reinterpret_cast<const uint4*>(&Wh[(size_t)ng * DD + k0 + lcol]);
            uint4 vl = *reinterpret_cast<const uint4*>(&Wl[(size_t)ng * DD + k0 + lcol]);
            *reinterpret_cast<uint4*>(&sBh[lrow * GSTRIDE + lcol]) = vh;
            *reinterpret_cast<uint4*>(&sBl[lrow * GSTRIDE + lcol]) = vl;
        }
        __syncthreads();

#pragma unroll
        for (int kt = 0; kt < 32; kt += 16) {
            u32 afh[2][4], afl[2][4], bfh[8], bfl[8];
#pragma unroll
            for (int mt = 0; mt < 2; mt++) {
                int row = wm * 32 + mt * 16 + (lane & 15);
                int col = kt + (lane >> 4) * 8;
                u32 off = (u32)(row * GSTRIDE + col) * 2;
                ldsm4(afh[mt], uAh + off);
                ldsm4(afl[mt], uAl + off);
            }
            {
                int g = lane >> 3, r = lane & 7;
                int row = wn * 32 + ((g >> 1) & 1) * 8 + r;
                int col = kt + (g & 1) * 8;
                u32 off = (u32)(row * GSTRIDE + col) * 2;
                u32 off2 = off + 16 * GSTRIDE * 2;
                ldsm4(&bfh[0], uBh + off);
                ldsm4(&bfl[0], uBl + off);
                ldsm4(&bfh[4], uBh + off2);
                ldsm4(&bfl[4], uBl + off2);
            }
#pragma unroll
            for (int mt = 0; mt < 2; mt++)
#pragma unroll
                for (int nt = 0; nt < 4; nt++) {
                    mma16816(acc[mt][nt], afh[mt], &bfh[nt * 2]);
                    mma16816(acc[mt][nt], afh[mt], &bfl[nt * 2]);
                    mma16816(acc[mt][nt], afl[mt], &bfh[nt * 2]);
                }
        }
        __syncthreads();
    }

    const int r = lane >> 2, c = (lane & 3) << 1;
#pragma unroll
    for (int mt = 0; mt < 2; mt++) {
#pragma unroll
        for (int nt = 0; nt < 4; nt++) {
            int n = n0 + wn * 32 + nt * 8 + c;
            float b0 = bias[n], b1 = bias[n + 1];
#pragma unroll
            for (int half = 0; half < 2; half++) {
                int m = m0 + wm * 32 + mt * 16 + r + half * 8;
                if (m >= NTOK) continue;
                float ox = (acc[mt][nt][half * 2] + b0) * scale;
                float oy = (acc[mt][nt][half * 2 + 1] + b1) * scale;
                if (mode == 0) {
                    int bidx = m / LL, l = m - bidx * LL;
                    int h = n >> 6, dd = n & 63;
                    size_t idx = ((size_t)(bidx * HH + h) * LL + l) * DKK + dd;
                    split_store2(CoutH, CoutL, idx, ox, oy);
                } else {
                    size_t off = (size_t)m * DD + n;
                    float2 r2 = *reinterpret_cast<const float2*>(&res[off]);
                    *reinterpret_cast<float2*>(&CoutF[off]) =
                        make_float2(ox + r2.x, oy + r2.y);
                }
            }
        }
    }
}

// --------------------------------------------------------- tensor-core flash attention
#define SSTR  72    // bf16 tile stride (rows 64 or 128)
#define SRSTR 132   // fp32 R-band stride

#define OFF_QH   0
#define OFF_QL   9216
#define OFF_KH   18432
#define OFF_KL   27648
#define OFF_VH   36864
#define OFF_VL   46080
#define OFF_PH   55296
#define OFF_PL   64512
#define OFF_REL  73728            // relh[128*72] + rell[128*72] bf16; aliased by R fp32 [64*132]
#define OFF_RELL (OFF_REL + 18432)
#define OFF_SM   110592
#define OFF_SL   110848
#define OFF_SMX  111104           // [128] fp32
#define OFF_SSUM 111616           // [128] fp32
#define ATTN_SMEM 112128

__global__ __launch_bounds__(256, 2) void attn_tc_kernel(
    const __nv_bfloat16* __restrict__ relh, const __nv_bfloat16* __restrict__ rell)
{
    extern __shared__ __align__(16) char smem[];
    __nv_bfloat16* sQh = (__nv_bfloat16*)(smem + OFF_QH);
    __nv_bfloat16* sQl = (__nv_bfloat16*)(smem + OFF_QL);
    __nv_bfloat16* sKh = (__nv_bfloat16*)(smem + OFF_KH);
    __nv_bfloat16* sKl = (__nv_bfloat16*)(smem + OFF_KL);
    __nv_bfloat16* sVh = (__nv_bfloat16*)(smem + OFF_VH);
    __nv_bfloat16* sVl = (__nv_bfloat16*)(smem + OFF_VL);
    __nv_bfloat16* sPh = (__nv_bfloat16*)(smem + OFF_PH);
    __nv_bfloat16* sPl = (__nv_bfloat16*)(smem + OFF_PL);
    __nv_bfloat16* sRh = (__nv_bfloat16*)(smem + OFF_REL);
    __nv_bfloat16* sRl = (__nv_bfloat16*)(smem + OFF_RELL);
    float* sR   = (float*)(smem + OFF_REL);   // alias over rel planes
    float* sm_  = (float*)(smem + OFF_SM);
    float* sl_  = (float*)(smem + OFF_SL);
    float* smx  = (float*)(smem + OFF_SMX);
    float* ssum = (float*)(smem + OFF_SSUM);

    const int tid = threadIdx.x;
    const int lane = tid & 31, wid = tid >> 5;
    const int wm = wid & 3, wn = wid >> 2;
    const int bh = blockIdx.y;
    const int i0 = blockIdx.x << 6;
    const u32 sb = (u32)__cvta_generic_to_shared(smem);

    const __nv_bfloat16* qh = g_qh + (size_t)bh * LL * DKK;
    const __nv_bfloat16* ql = g_ql + (size_t)bh * LL * DKK;
    const __nv_bfloat16* kh = g_kh + (size_t)bh * LL * DKK;
    const __nv_bfloat16* kl = g_kl + (size_t)bh * LL * DKK;
    const __nv_bfloat16* vh = g_vh + (size_t)bh * LL * DKK;
    const __nv_bfloat16* vl = g_vl + (size_t)bh * LL * DKK;

    if (tid < 64) { sm_[tid] = -1e30f; sl_[tid] = 0.f; }

    // Q tile
#pragma unroll
    for (int it = 0; it < 2; it++) {
        int idx = tid + it * 256;
        int r = idx >> 3, c = (idx & 7) << 3;
        int rg = i0 + r;
        uint4 h4 = make_uint4(0,0,0,0), l4 = make_uint4(0,0,0,0);
        if (rg < LL) {
            h4 = *reinterpret_cast<const uint4*>(&qh[(size_t)rg * DKK + c]);
            l4 = *reinterpret_cast<const uint4*>(&ql[(size_t)rg * DKK + c]);
        }
        *reinterpret_cast<uint4*>(&sQh[r * SSTR + c]) = h4;
        *reinterpret_cast<uint4*>(&sQl[r * SSTR + c]) = l4;
    }

    float oacc[4][4] = {};
    const int r4 = lane >> 2, c2 = (lane & 3) << 1;
    const int row0 = (wm << 4) + r4;           // local rows row0, row0+8

    for (int j0 = 0; j0 < LL; j0 += 64) {
        __syncthreads();
        // K, V tiles
#pragma unroll
        for (int it = 0; it < 2; it++) {
            int idx = tid + it * 256;
            int r = idx >> 3, c = (idx & 7) << 3;
            int jg = j0 + r;
            uint4 k4h = make_uint4(0,0,0,0), k4l = make_uint4(0,0,0,0);
            uint4 v4h = make_uint4(0,0,0,0), v4l = make_uint4(0,0,0,0);
            if (jg < LL) {
                k4h = *reinterpret_cast<const uint4*>(&kh[(size_t)jg * DKK + c]);
                k4l = *reinterpret_cast<const uint4*>(&kl[(size_t)jg * DKK + c]);
                v4h = *reinterpret_cast<const uint4*>(&vh[(size_t)jg * DKK + c]);
                v4l = *reinterpret_cast<const uint4*>(&vl[(size_t)jg * DKK + c]);
            }
            *reinterpret_cast<uint4*>(&sKh[r * SSTR + c]) = k4h;
            *reinterpret_cast<uint4*>(&sKl[r * SSTR + c]) = k4l;
            *reinterpret_cast<uint4*>(&sVh[r * SSTR + c]) = v4h;
            *reinterpret_cast<uint4*>(&sVl[r * SSTR + c]) = v4l;
        }
        // rel band (128 rows)
        int mbase = j0 - i0 + (LL - 1) - 63;
#pragma unroll
        for (int it = 0; it < 4; it++) {
            int idx = tid + it * 256;
            int r = idx >> 3, c = (idx & 7) << 3;
            int mg = mbase + r;
            uint4 h4 = make_uint4(0,0,0,0), l4 = make_uint4(0,0,0,0);
            if (mg >= 0 && mg < RELN) {
                h4 = *reinterpret_cast<const uint4*>(&relh[(size_t)mg * DKK + c]);
                l4 = *reinterpret_cast<const uint4*>(&rell[(size_t)mg * DKK + c]);
            }
            *reinterpret_cast<uint4*>(&sRh[r * SSTR + c]) = h4;
            *reinterpret_cast<uint4*>(&sRl[r * SSTR + c]) = l4;
        }
        __syncthreads();

        // phase 1: S = Q·K' (64x64), R = Q·rel (64x128)
        float sqk[4][4] = {};
        float rr[8][4] = {};
#pragma unroll
        for (int kc = 0; kc < 4; kc++) {
            u32 afh[4], afl[4];
            {
                int row = (wm << 4) + (lane & 15);
                int col = (kc << 4) + ((lane >> 4) << 3);
                u32 off = sb + (u32)(row * SSTR + col) * 2;
                ldsm4(afh, off + OFF_QH);
                ldsm4(afl, off + OFF_QL);
            }
            u32 bkh[8], bkl[8];
            {
                int g = lane >> 3, r8 = lane & 7;
                int row = (wn << 5) + (((g >> 1) & 1) << 3) + r8;
                int col = (kc << 4) + ((g & 1) << 3);
                u32 off = sb + (u32)(row * SSTR + col) * 2;
                ldsm4(&bkh[0], off + OFF_KH);
                ldsm4(&bkh[4], off + OFF_KH + 16 * SSTR * 2);
                ldsm4(&bkl[0], off + OFF_KL);
                ldsm4(&bkl[4], off + OFF_KL + 16 * SSTR * 2);
            }
#pragma unroll
            for (int nt = 0; nt < 4; nt++) {
                mma16816(sqk[nt], afh, &bkh[nt * 2]);
                mma16816(sqk[nt], afh, &bkl[nt * 2]);
                mma16816(sqk[nt], afl, &bkh[nt * 2]);
            }
#pragma unroll
            for (int gr = 0; gr < 4; gr++) {
                u32 rbh[4], rbl[4];
                int g = lane >> 3, r8 = lane & 7;
                int row = (wn << 6) + (gr << 4) + (((g >> 1) & 1) << 3) + r8;
                int col = (kc << 4) + ((g & 1) << 3);
                u32 off = sb + (u32)(row * SSTR + col) * 2;
                ldsm4(rbh, off + OFF_REL);
                ldsm4(rbl, off + OFF_RELL);
#pragma unroll
                for (int h2 = 0; h2 < 2; h2++) {
                    int nt = gr * 2 + h2;
                    mma16816(rr[nt], afh, &rbh[h2 * 2]);
                    mma16816(rr[nt], afh, &rbl[h2 * 2]);
                    mma16816(rr[nt], afl, &rbh[h2 * 2]);
                }
            }
        }
        __syncthreads();   // all rel ldsm done -> safe to alias
        // write R band fp32 over rel planes
#pragma unroll
        for (int nt = 0; nt < 8; nt++) {
            int colb = (wn << 6) + (nt << 3) + c2;
            *reinterpret_cast<float2*>(&sR[row0 * SRSTR + colb]) =
                make_float2(rr[nt][0], rr[nt][1]);
            *reinterpret_cast<float2*>(&sR[(row0 + 8) * SRSTR + colb]) =
                make_float2(rr[nt][2], rr[nt][3]);
        }
        __syncthreads();

        // softmax (fragment-level)
        float sc[2][8];
        {
            float mx0 = -1e30f, mx1 = -1e30f;
#pragma unroll
            for (int nt = 0; nt < 4; nt++) {
#pragma unroll
                for (int kk = 0; kk < 2; kk++) {
                    int c = (wn << 5) + (nt << 3) + c2 + kk;
                    bool valid = (j0 + c) < LL;
                    float v0 = sqk[nt][kk]     + sR[row0 * SRSTR + (c - row0 + 63)];
                    float v1 = sqk[nt][2 + kk] + sR[(row0 + 8) * SRSTR + (c - row0 - 8 + 63)];
                    v0 = valid ? v0 : -1e30f;
                    v1 = valid ? v1 : -1e30f;
                    sc[0][nt * 2 + kk] = v0;
                    sc[1][nt * 2 + kk] = v1;
                    mx0 = fmaxf(mx0, v0);
                    mx1 = fmaxf(mx1, v1);
                }
            }
            mx0 = fmaxf(mx0, __shfl_xor_sync(0xffffffffu, mx0, 1));
            mx0 = fmaxf(mx0, __shfl_xor_sync(0xffffffffu, mx0, 2));
            mx1 = fmaxf(mx1, __shfl_xor_sync(0xffffffffu, mx1, 1));
            mx1 = fmaxf(mx1, __shfl_xor_sync(0xffffffffu, mx1, 2));
            if ((lane & 3) == 0) {
                smx[(wn << 6) + row0]     = mx0;
                smx[(wn << 6) + row0 + 8] = mx1;
            }
        }
        __syncthreads();
        {
            float m0o = sm_[row0], m1o = sm_[row0 + 8];
            float m0n = fmaxf(m0o, fmaxf(smx[row0], smx[64 + row0]));
            float m1n = fmaxf(m1o, fmaxf(smx[row0 + 8], smx[64 + row0 + 8]));
            float corr0 = __expf(m0o - m0n), corr1 = __expf(m1o - m1n);
            float s0 = 0.f, s1 = 0.f;
#pragma unroll
            for (int nt = 0; nt < 4; nt++) {
                float p00 = __expf(sc[0][nt * 2]     - m0n);
                float p01 = __expf(sc[0][nt * 2 + 1] - m0n);
                float p10 = __expf(sc[1][nt * 2]     - m1n);
                float p11 = __expf(sc[1][nt * 2 + 1] - m1n);
                s0 += p00 + p01;
                s1 += p10 + p11;
                int colb = (wn << 5) + (nt << 3) + c2;
                split_store2(sPh, sPl, (size_t)(row0 * SSTR + colb), p00, p01);
                split_store2(sPh, sPl, (size_t)((row0 + 8) * SSTR + colb), p10, p11);
                oacc[nt][0] *= corr0; oacc[nt][1] *= corr0;
                oacc[nt][2] *= corr1; oacc[nt][3] *= corr1;
            }
            s0 += __shfl_xor_sync(0xffffffffu, s0, 1);
            s0 += __shfl_xor_sync(0xffffffffu, s0, 2);
            s1 += __shfl_xor_sync(0xffffffffu, s1, 1);
            s1 += __shfl_xor_sync(0xffffffffu, s1, 2);
            if ((lane & 3) == 0) {
                ssum[(wn << 6) + row0]     = s0;
                ssum[(wn << 6) + row0 + 8] = s1;
            }
        }
        __syncthreads();
        if (tid < 64) {
            float mo = sm_[tid];
            float mn = fmaxf(mo, fmaxf(smx[tid], smx[64 + tid]));
            sm_[tid] = mn;
            sl_[tid] = sl_[tid] * __expf(mo - mn) + ssum[tid] + ssum[64 + tid];
        }

        // PV: O += P @ V
#pragma unroll
        for (int kc = 0; kc < 4; kc++) {
            u32 pfh[4], pfl[4];
            {
                int row = (wm << 4) + (lane & 15);
                int col = (kc << 4) + ((lane >> 4) << 3);
                u32 off = sb + (u32)(row * SSTR + col) * 2;
                ldsm4(pfh, off + OFF_PH);
                ldsm4(pfl, off + OFF_PL);
            }
            u32 vbh[8], vbl[8];
            {
                int g = lane >> 3, r8 = lane & 7;
                int vrow = (kc << 4) + ((g & 1) << 3) + r8;
                int vcol = (wn << 5) + (((g >> 1) & 1) << 3);
                u32 off = sb + (u32)(vrow * SSTR + vcol) * 2;
                ldsm4t(&vbh[0], off + OFF_VH);
                ldsm4t(&vbh[4], off + OFF_VH + 16 * 2);
                ldsm4t(&vbl[0], off + OFF_VL);
                ldsm4t(&vbl[4], off + OFF_VL + 16 * 2);
            }
#pragma unroll
            for (int nt = 0; nt < 4; nt++) {
                mma16816(oacc[nt], pfh, &vbh[nt * 2]);
                mma16816(oacc[nt], pfh, &vbl[nt * 2]);
                mma16816(oacc[nt], pfl, &vbh[nt * 2]);
            }
        }
    }
    __syncthreads();

    // epilogue: normalize, split, write ctx planes
    int b = bh >> 3, h = bh & 7;
    float li0 = 1.0f / sl_[row0];
    float li1 = 1.0f / sl_[row0 + 8];
    int rg0 = i0 + row0, rg1 = rg0 + 8;
#pragma unroll
    for (int nt = 0; nt < 4; nt++) {
        int col = h * 64 + (wn << 5) + (nt << 3) + c2;
        if (rg0 < LL)
            split_store2(g_cth, g_ctl, ((size_t)(b * LL + rg0)) * DD + col,
                         oacc[nt][0] * li0, oacc[nt][1] * li0);
        if (rg1 < LL)
            split_store2(g_cth, g_ctl, ((size_t)(b * LL + rg1)) * DD + col,
                         oacc[nt][2] * li1, oacc[nt][3] * li1);
    }
}

// ---------------------------------------------------------------- launcher
extern "C" void kernel_launch(void* const* d_in, const int* in_sizes, int n_in,
                              void* d_out, int out_size)
{
    const float* x     = (const float*)d_in[0];
    const float* Wq    = (const float*)d_in[1];
    const float* bq    = (const float*)d_in[2];
    const float* Wk    = (const float*)d_in[3];
    const float* bk    = (const float*)d_in[4];
    const float* Wv    = (const float*)d_in[5];
    const float* bv    = (const float*)d_in[6];
    const float* Wo    = (const float*)d_in[7];
    const float* bo    = (const float*)d_in[8];
    const float* rel   = (const float*)d_in[9];
    const float* gamma = (const float*)d_in[10];
    const float* beta  = (const float*)d_in[11];
    float* out = (float*)d_out;

    __nv_bfloat16 *xnh, *xnl, *qh, *ql, *kh, *kl, *vh, *vl, *cth, *ctl, *wh, *wl, *relh, *rell;
    cudaGetSymbolAddress((void**)&xnh, g_xnh);
    cudaGetSymbolAddress((void**)&xnl, g_xnl);
    cudaGetSymbolAddress((void**)&qh,  g_qh);
    cudaGetSymbolAddress((void**)&ql,  g_ql);
    cudaGetSymbolAddress((void**)&kh,  g_kh);
    cudaGetSymbolAddress((void**)&kl,  g_kl);
    cudaGetSymbolAddress((void**)&vh,  g_vh);
    cudaGetSymbolAddress((void**)&vl,  g_vl);
    cudaGetSymbolAddress((void**)&cth, g_cth);
    cudaGetSymbolAddress((void**)&ctl, g_ctl);
    cudaGetSymbolAddress((void**)&wh,  g_wh);
    cudaGetSymbolAddress((void**)&wl,  g_wl);
    cudaGetSymbolAddress((void**)&relh, g_relh);
    cudaGetSymbolAddress((void**)&rell, g_rell);

    cudaFuncSetAttribute(attn_tc_kernel, cudaFuncAttributeMaxDynamicSharedMemorySize,
                         ATTN_SMEM);

    ln_kernel<<<NTOK, 128>>>(x, gamma, beta);
    split_kernel<<<256, 256>>>(Wq, wh + 0*DD*DD, wl + 0*DD*DD, DD*DD/4);
    split_kernel<<<256, 256>>>(Wk, wh + 1*DD*DD, wl + 1*DD*DD, DD*DD/4);
    split_kernel<<<256, 256>>>(Wv, wh + 2*DD*DD, wl + 2*DD*DD, DD*DD/4);
    split_kernel<<<256, 256>>>(Wo, wh + 3*DD*DD, wl + 3*DD*DD, DD*DD/4);
    split_kernel<<<125, 256>>>(rel, relh, rell, RELN*DKK/4);

    dim3 gg(DD / 64, (NTOK + 127) / 128);  // (8, 63)
    gemm_tc_kernel<<<gg, 256>>>(xnh, xnl, wh + 0*DD*DD, wl + 0*DD*DD, bq,
                                nullptr, nullptr, qh, ql, 1.0f, 0);
    gemm_tc_kernel<<<gg, 256>>>(xnh, xnl, wh + 1*DD*DD, wl + 1*DD*DD, bk,
                                nullptr, nullptr, kh, kl, 0.125f, 0);
    gemm_tc_kernel<<<gg, 256>>>(xnh, xnl, wh + 2*DD*DD, wl + 2*DD*DD, bv,
                                nullptr, nullptr, vh, vl, 1.0f, 0);

    dim3 ga((LL + 63) / 64, BB * HH);  // (16, 64)
    attn_tc_kernel<<<ga, 256, ATTN_SMEM>>>(relh, rell);

    gemm_tc_kernel<<<gg, 256>>>(cth, ctl, wh + 3*DD*DD, wl + 3*DD*DD, bo,
                                out, x, nullptr, nullptr, 1.0f, 1);
}

// round 5
// speedup vs baseline: 3.1895x; 1.7309x over previous
#include <cuda_runtime.h>
#include <cuda_bf16.h>
#include <math.h>

#define BB 8
#define LL 1000
#define DD 512
#define HH 8
#define DKK 64
#define NTOK (BB*LL)
#define RELN (2*LL-1)

typedef unsigned int u32;

// ------------------------------------------------------------ scratch (bf16 hi/lo planes)
__device__ __nv_bfloat16 g_xnh[NTOK*DD];
__device__ __nv_bfloat16 g_xnl[NTOK*DD];
__device__ __nv_bfloat16 g_qh[NTOK*DD];  // (B,H,L,dk)
__device__ __nv_bfloat16 g_ql[NTOK*DD];
__device__ __nv_bfloat16 g_kh[NTOK*DD];  // pre-scaled by 1/8
__device__ __nv_bfloat16 g_kl[NTOK*DD];
__device__ __nv_bfloat16 g_vh[NTOK*DD];
__device__ __nv_bfloat16 g_vl[NTOK*DD];
__device__ __nv_bfloat16 g_cth[NTOK*DD]; // ctx (B,L,D)
__device__ __nv_bfloat16 g_ctl[NTOK*DD];
__device__ __nv_bfloat16 g_wh[4*DD*DD];  // [Wq;Wk;Wv;Wo] hi
__device__ __nv_bfloat16 g_wl[4*DD*DD];
__device__ __nv_bfloat16 g_relh[RELN*DKK];
__device__ __nv_bfloat16 g_rell[RELN*DKK];

// ------------------------------------------------------------ asm helpers
__device__ __forceinline__ void mma16816(float* d, const u32* a, const u32* b) {
    asm volatile(
        "mma.sync.aligned.m16n8k16.row.col.f32.bf16.bf16.f32 "
        "{%0,%1,%2,%3}, {%4,%5,%6,%7}, {%8,%9}, {%0,%1,%2,%3};"
        : "+f"(d[0]), "+f"(d[1]), "+f"(d[2]), "+f"(d[3])
        : "r"(a[0]), "r"(a[1]), "r"(a[2]), "r"(a[3]), "r"(b[0]), "r"(b[1]));
}
__device__ __forceinline__ void ldsm4(u32* r, u32 addr) {
    asm volatile("ldmatrix.sync.aligned.m8n8.x4.shared.b16 {%0,%1,%2,%3}, [%4];"
                 : "=r"(r[0]), "=r"(r[1]), "=r"(r[2]), "=r"(r[3]) : "r"(addr));
}
__device__ __forceinline__ void ldsm4t(u32* r, u32 addr) {
    asm volatile("ldmatrix.sync.aligned.m8n8.x4.trans.shared.b16 {%0,%1,%2,%3}, [%4];"
                 : "=r"(r[0]), "=r"(r[1]), "=r"(r[2]), "=r"(r[3]) : "r"(addr));
}
__device__ __forceinline__ void cpa16(u32 dst, const void* src, int sz) {
    asm volatile("cp.async.cg.shared.global [%0], [%1], 16, %2;"
                 :: "r"(dst), "l"(src), "r"(sz));
}
__device__ __forceinline__ void cp_commit() {
    asm volatile("cp.async.commit_group;");
}
template <int N> __device__ __forceinline__ void cp_wait() {
    asm volatile("cp.async.wait_group %0;" :: "n"(N));
}
__device__ __forceinline__ void split_store2(__nv_bfloat16* H, __nv_bfloat16* L,
                                             size_t idx, float x, float y) {
    __nv_bfloat16 hx = __float2bfloat16_rn(x), hy = __float2bfloat16_rn(y);
    *reinterpret_cast<__nv_bfloat162*>(&H[idx]) = __halves2bfloat162(hx, hy);
    *reinterpret_cast<__nv_bfloat162*>(&L[idx]) = __halves2bfloat162(
        __float2bfloat16_rn(x - __bfloat162float(hx)),
        __float2bfloat16_rn(y - __bfloat162float(hy)));
}

// ------------------------------------------------------------ LayerNorm + bf16 split
__global__ __launch_bounds__(128) void ln_kernel(const float* __restrict__ x,
                                                 const float* __restrict__ gamma,
                                                 const float* __restrict__ beta)
{
    int tok = blockIdx.x;
    int tid = threadIdx.x;
    const float4 v = reinterpret_cast<const float4*>(x + (size_t)tok * DD)[tid];
    float s  = v.x + v.y + v.z + v.w;
    float ss = v.x*v.x + v.y*v.y + v.z*v.z + v.w*v.w;
#pragma unroll
    for (int o = 16; o; o >>= 1) {
        s  += __shfl_xor_sync(0xffffffffu, s,  o);
        ss += __shfl_xor_sync(0xffffffffu, ss, o);
    }
    __shared__ float sh[8];
    int w = tid >> 5, lane = tid & 31;
    if (lane == 0) { sh[w] = s; sh[4 + w] = ss; }
    __syncthreads();
    s  = sh[0] + sh[1] + sh[2] + sh[3];
    ss = sh[4] + sh[5] + sh[6] + sh[7];
    float mu  = s * (1.0f / DD);
    float var = ss * (1.0f / DD) - mu * mu;
    float inv = rsqrtf(var + 1e-5f);
    float4 g = reinterpret_cast<const float4*>(gamma)[tid];
    float4 b = reinterpret_cast<const float4*>(beta)[tid];
    float o0 = (v.x - mu) * inv * g.x + b.x;
    float o1 = (v.y - mu) * inv * g.y + b.y;
    float o2 = (v.z - mu) * inv * g.z + b.z;
    float o3 = (v.w - mu) * inv * g.w + b.w;
    size_t base = (size_t)tok * DD + tid * 4;
    split_store2(g_xnh, g_xnl, base,     o0, o1);
    split_store2(g_xnh, g_xnl, base + 2, o2, o3);
}

// ------------------------------------------------------------ fp32 -> bf16 hi/lo split
__global__ __launch_bounds__(256) void split_kernel(const float* __restrict__ src,
                                                    __nv_bfloat16* __restrict__ hi,
                                                    __nv_bfloat16* __restrict__ lo,
                                                    int n4)
{
    int iv = blockIdx.x * blockDim.x + threadIdx.x;
    if (iv >= n4) return;
    size_t i = (size_t)iv * 4;
    float4 v = *reinterpret_cast<const float4*>(src + i);
    split_store2(hi, lo, i,     v.x, v.y);
    split_store2(hi, lo, i + 2, v.z, v.w);
}

// ------------------------------------------------------------ pipelined fused GEMM
// C(8000 x N) = A @ W^T, 128x128 block tile, BK=32, 2-stage cp.async pipeline.
// 8 warps as 2m x 4n; warp tile 64x32. 3-term bf16-split MMA.
// mode 0: N=1536 stacked QKV weights -> bf16 hi/lo planes (B,H,L,dk), K scaled 1/8
// mode 1: N=512 Wo -> fp32 out + residual
#define GS 40                       // smem row stride (bf16), 80B
#define PL (128 * GS)               // one plane (elems)
#define AH_OFF 0
#define AL_OFF (PL * 2)             // bytes
#define BH_OFF (PL * 4)
#define BL_OFF (PL * 6)
#define STAGE_B (PL * 8)            // 40960 bytes per stage
#define GEMM_SMEM (2 * STAGE_B)

__global__ __launch_bounds__(256, 2) void gemm_tc_kernel(
    const __nv_bfloat16* __restrict__ Ah, const __nv_bfloat16* __restrict__ Al,
    const __nv_bfloat16* __restrict__ Wh, const __nv_bfloat16* __restrict__ Wl,
    const float* __restrict__ b0, const float* __restrict__ b1,
    const float* __restrict__ b2,
    float* __restrict__ CoutF, const float* __restrict__ res,
    __nv_bfloat16* __restrict__ Qh, __nv_bfloat16* __restrict__ Ql,
    __nv_bfloat16* __restrict__ Kh, __nv_bfloat16* __restrict__ Kl,
    __nv_bfloat16* __restrict__ Vh, __nv_bfloat16* __restrict__ Vl,
    int mode)
{
    extern __shared__ __align__(16) char smem[];
    const u32 sb = (u32)__cvta_generic_to_shared(smem);

    const int tid = threadIdx.x;
    const int lane = tid & 31, wid = tid >> 5;
    const int wm = wid & 1, wn = wid >> 1;       // 2m x 4n
    const int m0 = blockIdx.y * 128;
    const int n0 = blockIdx.x * 128;

    const int lr = tid >> 2;                     // 0..63
    const int lc = (tid & 3) << 3;               // 0,8,16,24

    float acc[4][4][4] = {};

    // --- stage loader ---
    auto load_stage = [&](int k0, int s) {
        u32 base = sb + s * STAGE_B;
#pragma unroll
        for (int it = 0; it < 2; it++) {
            int r = lr + it * 64;
            u32 soff = (u32)(r * GS + lc) * 2;
            int mg = m0 + r;
            int mclamp = mg < NTOK ? mg : NTOK - 1;
            int sz = mg < NTOK ? 16 : 0;
            cpa16(base + AH_OFF + soff, &Ah[(size_t)mclamp * DD + k0 + lc], sz);
            cpa16(base + AL_OFF + soff, &Al[(size_t)mclamp * DD + k0 + lc], sz);
            int ng = n0 + r;
            cpa16(base + BH_OFF + soff, &Wh[(size_t)ng * DD + k0 + lc], 16);
            cpa16(base + BL_OFF + soff, &Wl[(size_t)ng * DD + k0 + lc], 16);
        }
        cp_commit();
    };

    load_stage(0, 0);

#pragma unroll 1
    for (int ks = 0; ks < 16; ks++) {
        if (ks + 1 < 16) load_stage((ks + 1) * 32, (ks + 1) & 1);
        if (ks + 1 < 16) cp_wait<1>(); else cp_wait<0>();
        __syncthreads();

        u32 base = sb + (ks & 1) * STAGE_B;
#pragma unroll
        for (int kt = 0; kt < 32; kt += 16) {
            u32 bfh[8], bfl[8];
            {
                int g = lane >> 3, r8 = lane & 7;
                int brow = wn * 32 + ((g >> 1) & 1) * 8 + r8;
                int bcol = kt + (g & 1) * 8;
                u32 boff = base + (u32)(brow * GS + bcol) * 2;
                ldsm4(&bfh[0], boff + BH_OFF);
                ldsm4(&bfh[4], boff + BH_OFF + 16 * GS * 2);
                ldsm4(&bfl[0], boff + BL_OFF);
                ldsm4(&bfl[4], boff + BL_OFF + 16 * GS * 2);
            }
#pragma unroll
            for (int mt = 0; mt < 4; mt++) {
                u32 afh[4], afl[4];
                int arow = wm * 64 + mt * 16 + (lane & 15);
                int acol = kt + ((lane >> 4) << 3);
                u32 aoff = base + (u32)(arow * GS + acol) * 2;
                ldsm4(afh, aoff + AH_OFF);
                ldsm4(afl, aoff + AL_OFF);
#pragma unroll
                for (int nt = 0; nt < 4; nt++) {
                    mma16816(acc[mt][nt], afh, &bfh[nt * 2]);
                    mma16816(acc[mt][nt], afh, &bfl[nt * 2]);
                    mma16816(acc[mt][nt], afl, &bfh[nt * 2]);
                }
            }
        }
        __syncthreads();
    }

    // --- epilogue ---
    const int r = lane >> 2, c = (lane & 3) << 1;
    if (mode == 0) {
        int wsel = n0 >> 9;
        const float* bias = wsel == 0 ? b0 : (wsel == 1 ? b1 : b2);
        float scl = wsel == 1 ? 0.125f : 1.0f;
        __nv_bfloat16* OH = wsel == 0 ? Qh : (wsel == 1 ? Kh : Vh);
        __nv_bfloat16* OL = wsel == 0 ? Ql : (wsel == 1 ? Kl : Vl);
        int nl0 = (n0 & 511) + wn * 32;
#pragma unroll
        for (int mt = 0; mt < 4; mt++) {
#pragma unroll
            for (int nt = 0; nt < 4; nt++) {
                int nl = nl0 + nt * 8 + c;
                float bb0 = bias[nl], bb1 = bias[nl + 1];
                int h = nl >> 6, dd = nl & 63;
#pragma unroll
                for (int half = 0; half < 2; half++) {
                    int m = m0 + wm * 64 + mt * 16 + r + half * 8;
                    if (m >= NTOK) continue;
                    int bidx = m / LL, l = m - bidx * LL;
                    float ox = (acc[mt][nt][half * 2]     + bb0) * scl;
                    float oy = (acc[mt][nt][half * 2 + 1] + bb1) * scl;
                    size_t idx = ((size_t)(bidx * HH + h) * LL + l) * DKK + dd;
                    split_store2(OH, OL, idx, ox, oy);
                }
            }
        }
    } else {
#pragma unroll
        for (int mt = 0; mt < 4; mt++) {
#pragma unroll
            for (int nt = 0; nt < 4; nt++) {
                int n = n0 + wn * 32 + nt * 8 + c;
                float bb0 = b0[n], bb1 = b0[n + 1];
#pragma unroll
                for (int half = 0; half < 2; half++) {
                    int m = m0 + wm * 64 + mt * 16 + r + half * 8;
                    if (m >= NTOK) continue;
                    size_t off = (size_t)m * DD + n;
                    float2 r2 = *reinterpret_cast<const float2*>(&res[off]);
                    *reinterpret_cast<float2*>(&CoutF[off]) =
                        make_float2(acc[mt][nt][half * 2] + bb0 + r2.x,
                                    acc[mt][nt][half * 2 + 1] + bb1 + r2.y);
                }
            }
        }
    }
}

// --------------------------------------------------------- tensor-core flash attention
#define SSTR  72    // bf16 tile stride
#define SRSTR 132   // fp32 R-band stride

#define OFF_QH   0
#define OFF_QL   9216
#define OFF_KH   18432
#define OFF_KL   27648
#define OFF_VH   36864
#define OFF_VL   46080
#define OFF_PH   55296
#define OFF_PL   64512
#define OFF_REL  73728
#define OFF_RELL (OFF_REL + 18432)
#define OFF_SM   110592
#define OFF_SL   110848
#define OFF_SMX  111104
#define OFF_SSUM 111616
#define ATTN_SMEM 112128

__global__ __launch_bounds__(256, 2) void attn_tc_kernel(
    const __nv_bfloat16* __restrict__ relh, const __nv_bfloat16* __restrict__ rell)
{
    extern __shared__ __align__(16) char smem[];
    __nv_bfloat16* sQh = (__nv_bfloat16*)(smem + OFF_QH);
    __nv_bfloat16* sQl = (__nv_bfloat16*)(smem + OFF_QL);
    __nv_bfloat16* sKh = (__nv_bfloat16*)(smem + OFF_KH);
    __nv_bfloat16* sKl = (__nv_bfloat16*)(smem + OFF_KL);
    __nv_bfloat16* sVh = (__nv_bfloat16*)(smem + OFF_VH);
    __nv_bfloat16* sVl = (__nv_bfloat16*)(smem + OFF_VL);
    __nv_bfloat16* sPh = (__nv_bfloat16*)(smem + OFF_PH);
    __nv_bfloat16* sPl = (__nv_bfloat16*)(smem + OFF_PL);
    __nv_bfloat16* sRh = (__nv_bfloat16*)(smem + OFF_REL);
    __nv_bfloat16* sRl = (__nv_bfloat16*)(smem + OFF_RELL);
    float* sR   = (float*)(smem + OFF_REL);
    float* sm_  = (float*)(smem + OFF_SM);
    float* sl_  = (float*)(smem + OFF_SL);
    float* smx  = (float*)(smem + OFF_SMX);
    float* ssum = (float*)(smem + OFF_SSUM);

    const int tid = threadIdx.x;
    const int lane = tid & 31, wid = tid >> 5;
    const int wm = wid & 3, wn = wid >> 2;
    const int bh = blockIdx.y;
    const int i0 = blockIdx.x << 6;
    const u32 sb = (u32)__cvta_generic_to_shared(smem);

    const __nv_bfloat16* qh = g_qh + (size_t)bh * LL * DKK;
    const __nv_bfloat16* ql = g_ql + (size_t)bh * LL * DKK;
    const __nv_bfloat16* kh = g_kh + (size_t)bh * LL * DKK;
    const __nv_bfloat16* kl = g_kl + (size_t)bh * LL * DKK;
    const __nv_bfloat16* vh = g_vh + (size_t)bh * LL * DKK;
    const __nv_bfloat16* vl = g_vl + (size_t)bh * LL * DKK;

    if (tid < 64) { sm_[tid] = -1e30f; sl_[tid] = 0.f; }

#pragma unroll
    for (int it = 0; it < 2; it++) {
        int idx = tid + it * 256;
        int r = idx >> 3, c = (idx & 7) << 3;
        int rg = i0 + r;
        uint4 h4 = make_uint4(0,0,0,0), l4 = make_uint4(0,0,0,0);
        if (rg < LL) {
            h4 = *reinterpret_cast<const uint4*>(&qh[(size_t)rg * DKK + c]);
            l4 = *reinterpret_cast<const uint4*>(&ql[(size_t)rg * DKK + c]);
        }
        *reinterpret_cast<uint4*>(&sQh[r * SSTR + c]) = h4;
        *reinterpret_cast<uint4*>(&sQl[r * SSTR + c]) = l4;
    }

    float oacc[4][4] = {};
    const int r4 = lane >> 2, c2 = (lane & 3) << 1;
    const int row0 = (wm << 4) + r4;

    for (int j0 = 0; j0 < LL; j0 += 64) {
        __syncthreads();
#pragma unroll
        for (int it = 0; it < 2; it++) {
            int idx = tid + it * 256;
            int r = idx >> 3, c = (idx & 7) << 3;
            int jg = j0 + r;
            uint4 k4h = make_uint4(0,0,0,0), k4l = make_uint4(0,0,0,0);
            uint4 v4h = make_uint4(0,0,0,0), v4l = make_uint4(0,0,0,0);
            if (jg < LL) {
                k4h = *reinterpret_cast<const uint4*>(&kh[(size_t)jg * DKK + c]);
                k4l = *reinterpret_cast<const uint4*>(&kl[(size_t)jg * DKK + c]);
                v4h = *reinterpret_cast<const uint4*>(&vh[(size_t)jg * DKK + c]);
                v4l = *reinterpret_cast<const uint4*>(&vl[(size_t)jg * DKK + c]);
            }
            *reinterpret_cast<uint4*>(&sKh[r * SSTR + c]) = k4h;
            *reinterpret_cast<uint4*>(&sKl[r * SSTR + c]) = k4l;
            *reinterpret_cast<uint4*>(&sVh[r * SSTR + c]) = v4h;
            *reinterpret_cast<uint4*>(&sVl[r * SSTR + c]) = v4l;
        }
        int mbase = j0 - i0 + (LL - 1) - 63;
#pragma unroll
        for (int it = 0; it < 4; it++) {
            int idx = tid + it * 256;
            int r = idx >> 3, c = (idx & 7) << 3;
            int mg = mbase + r;
            uint4 h4 = make_uint4(0,0,0,0), l4 = make_uint4(0,0,0,0);
            if (mg >= 0 && mg < RELN) {
                h4 = *reinterpret_cast<const uint4*>(&relh[(size_t)mg * DKK + c]);
                l4 = *reinterpret_cast<const uint4*>(&rell[(size_t)mg * DKK + c]);
            }
            *reinterpret_cast<uint4*>(&sRh[r * SSTR + c]) = h4;
            *reinterpret_cast<uint4*>(&sRl[r * SSTR + c]) = l4;
        }
        __syncthreads();

        float sqk[4][4] = {};
        float rr[8][4] = {};
#pragma unroll
        for (int kc = 0; kc < 4; kc++) {
            u32 afh[4], afl[4];
            {
                int row = (wm << 4) + (lane & 15);
                int col = (kc << 4) + ((lane >> 4) << 3);
                u32 off = sb + (u32)(row * SSTR + col) * 2;
                ldsm4(afh, off + OFF_QH);
                ldsm4(afl, off + OFF_QL);
            }
            u32 bkh[8], bkl[8];
            {
                int g = lane >> 3, r8 = lane & 7;
                int row = (wn << 5) + (((g >> 1) & 1) << 3) + r8;
                int col = (kc << 4) + ((g & 1) << 3);
                u32 off = sb + (u32)(row * SSTR + col) * 2;
                ldsm4(&bkh[0], off + OFF_KH);
                ldsm4(&bkh[4], off + OFF_KH + 16 * SSTR * 2);
                ldsm4(&bkl[0], off + OFF_KL);
                ldsm4(&bkl[4], off + OFF_KL + 16 * SSTR * 2);
            }
#pragma unroll
            for (int nt = 0; nt < 4; nt++) {
                mma16816(sqk[nt], afh, &bkh[nt * 2]);
                mma16816(sqk[nt], afh, &bkl[nt * 2]);
                mma16816(sqk[nt], afl, &bkh[nt * 2]);
            }
#pragma unroll
            for (int gr = 0; gr < 4; gr++) {
                u32 rbh[4], rbl[4];
                int g = lane >> 3, r8 = lane & 7;
                int row = (wn << 6) + (gr << 4) + (((g >> 1) & 1) << 3) + r8;
                int col = (kc << 4) + ((g & 1) << 3);
                u32 off = sb + (u32)(row * SSTR + col) * 2;
                ldsm4(rbh, off + OFF_REL);
                ldsm4(rbl, off + OFF_RELL);
#pragma unroll
                for (int h2 = 0; h2 < 2; h2++) {
                    int nt = gr * 2 + h2;
                    mma16816(rr[nt], afh, &rbh[h2 * 2]);
                    mma16816(rr[nt], afh, &rbl[h2 * 2]);
                    mma16816(rr[nt], afl, &rbh[h2 * 2]);
                }
            }
        }
        __syncthreads();
#pragma unroll
        for (int nt = 0; nt < 8; nt++) {
            int colb = (wn << 6) + (nt << 3) + c2;
            *reinterpret_cast<float2*>(&sR[row0 * SRSTR + colb]) =
                make_float2(rr[nt][0], rr[nt][1]);
            *reinterpret_cast<float2*>(&sR[(row0 + 8) * SRSTR + colb]) =
                make_float2(rr[nt][2], rr[nt][3]);
        }
        __syncthreads();

        float sc[2][8];
        {
            float mx0 = -1e30f, mx1 = -1e30f;
#pragma unroll
            for (int nt = 0; nt < 4; nt++) {
#pragma unroll
                for (int kk = 0; kk < 2; kk++) {
                    int c = (wn << 5) + (nt << 3) + c2 + kk;
                    bool valid = (j0 + c) < LL;
                    float v0 = sqk[nt][kk]     + sR[row0 * SRSTR + (c - row0 + 63)];
                    float v1 = sqk[nt][2 + kk] + sR[(row0 + 8) * SRSTR + (c - row0 - 8 + 63)];
                    v0 = valid ? v0 : -1e30f;
                    v1 = valid ? v1 : -1e30f;
                    sc[0][nt * 2 + kk] = v0;
                    sc[1][nt * 2 + kk] = v1;
                    mx0 = fmaxf(mx0, v0);
                    mx1 = fmaxf(mx1, v1);
                }
            }
            mx0 = fmaxf(mx0, __shfl_xor_sync(0xffffffffu, mx0, 1));
            mx0 = fmaxf(mx0, __shfl_xor_sync(0xffffffffu, mx0, 2));
            mx1 = fmaxf(mx1, __shfl_xor_sync(0xffffffffu, mx1, 1));
            mx1 = fmaxf(mx1, __shfl_xor_sync(0xffffffffu, mx1, 2));
            if ((lane & 3) == 0) {
                smx[(wn << 6) + row0]     = mx0;
                smx[(wn << 6) + row0 + 8] = mx1;
            }
        }
        __syncthreads();
        {
            float m0o = sm_[row0], m1o = sm_[row0 + 8];
            float m0n = fmaxf(m0o, fmaxf(smx[row0], smx[64 + row0]));
            float m1n = fmaxf(m1o, fmaxf(smx[row0 + 8], smx[64 + row0 + 8]));
            float corr0 = __expf(m0o - m0n), corr1 = __expf(m1o - m1n);
            float s0 = 0.f, s1 = 0.f;
#pragma unroll
            for (int nt = 0; nt < 4; nt++) {
                float p00 = __expf(sc[0][nt * 2]     - m0n);
                float p01 = __expf(sc[0][nt * 2 + 1] - m0n);
                float p10 = __expf(sc[1][nt * 2]     - m1n);
                float p11 = __expf(sc[1][nt * 2 + 1] - m1n);
                s0 += p00 + p01;
                s1 += p10 + p11;
                int colb = (wn << 5) + (nt << 3) + c2;
                split_store2(sPh, sPl, (size_t)(row0 * SSTR + colb), p00, p01);
                split_store2(sPh, sPl, (size_t)((row0 + 8) * SSTR + colb), p10, p11);
                oacc[nt][0] *= corr0; oacc[nt][1] *= corr0;
                oacc[nt][2] *= corr1; oacc[nt][3] *= corr1;
            }
            s0 += __shfl_xor_sync(0xffffffffu, s0, 1);
            s0 += __shfl_xor_sync(0xffffffffu, s0, 2);
            s1 += __shfl_xor_sync(0xffffffffu, s1, 1);
            s1 += __shfl_xor_sync(0xffffffffu, s1, 2);
            if ((lane & 3) == 0) {
                ssum[(wn << 6) + row0]     = s0;
                ssum[(wn << 6) + row0 + 8] = s1;
            }
        }
        __syncthreads();
        if (tid < 64) {
            float mo = sm_[tid];
            float mn = fmaxf(mo, fmaxf(smx[tid], smx[64 + tid]));
            sm_[tid] = mn;
            sl_[tid] = sl_[tid] * __expf(mo - mn) + ssum[tid] + ssum[64 + tid];
        }

#pragma unroll
        for (int kc = 0; kc < 4; kc++) {
            u32 pfh[4], pfl[4];
            {
                int row = (wm << 4) + (lane & 15);
                int col = (kc << 4) + ((lane >> 4) << 3);
                u32 off = sb + (u32)(row * SSTR + col) * 2;
                ldsm4(pfh, off + OFF_PH);
                ldsm4(pfl, off + OFF_PL);
            }
            u32 vbh[8], vbl[8];
            {
                int g = lane >> 3, r8 = lane & 7;
                int vrow = (kc << 4) + ((g & 1) << 3) + r8;
                int vcol = (wn << 5) + (((g >> 1) & 1) << 3);
                u32 off = sb + (u32)(vrow * SSTR + vcol) * 2;
                ldsm4t(&vbh[0], off + OFF_VH);
                ldsm4t(&vbh[4], off + OFF_VH + 16 * 2);
                ldsm4t(&vbl[0], off + OFF_VL);
                ldsm4t(&vbl[4], off + OFF_VL + 16 * 2);
            }
#pragma unroll
            for (int nt = 0; nt < 4; nt++) {
                mma16816(oacc[nt], pfh, &vbh[nt * 2]);
                mma16816(oacc[nt], pfh, &vbl[nt * 2]);
                mma16816(oacc[nt], pfl, &vbh[nt * 2]);
            }
        }
    }
    __syncthreads();

    int b = bh >> 3, h = bh & 7;
    float li0 = 1.0f / sl_[row0];
    float li1 = 1.0f / sl_[row0 + 8];
    int rg0 = i0 + row0, rg1 = rg0 + 8;
#pragma unroll
    for (int nt = 0; nt < 4; nt++) {
        int col = h * 64 + (wn << 5) + (nt << 3) + c2;
        if (rg0 < LL)
            split_store2(g_cth, g_ctl, ((size_t)(b * LL + rg0)) * DD + col,
                         oacc[nt][0] * li0, oacc[nt][1] * li0);
        if (rg1 < LL)
            split_store2(g_cth, g_ctl, ((size_t)(b * LL + rg1)) * DD + col,
                         oacc[nt][2] * li1, oacc[nt][3] * li1);
    }
}

// ---------------------------------------------------------------- launcher
extern "C" void kernel_launch(void* const* d_in, const int* in_sizes, int n_in,
                              void* d_out, int out_size)
{
    const float* x     = (const float*)d_in[0];
    const float* Wq    = (const float*)d_in[1];
    const float* bq    = (const float*)d_in[2];
    const float* Wk    = (const float*)d_in[3];
    const float* bk    = (const float*)d_in[4];
    const float* Wv    = (const float*)d_in[5];
    const float* bv    = (const float*)d_in[6];
    const float* Wo    = (const float*)d_in[7];
    const float* bo    = (const float*)d_in[8];
    const float* rel   = (const float*)d_in[9];
    const float* gamma = (const float*)d_in[10];
    const float* beta  = (const float*)d_in[11];
    float* out = (float*)d_out;

    __nv_bfloat16 *xnh, *xnl, *qh, *ql, *kh, *kl, *vh, *vl, *cth, *ctl, *wh, *wl, *relh, *rell;
    cudaGetSymbolAddress((void**)&xnh, g_xnh);
    cudaGetSymbolAddress((void**)&xnl, g_xnl);
    cudaGetSymbolAddress((void**)&qh,  g_qh);
    cudaGetSymbolAddress((void**)&ql,  g_ql);
    cudaGetSymbolAddress((void**)&kh,  g_kh);
    cudaGetSymbolAddress((void**)&kl,  g_kl);
    cudaGetSymbolAddress((void**)&vh,  g_vh);
    cudaGetSymbolAddress((void**)&vl,  g_vl);
    cudaGetSymbolAddress((void**)&cth, g_cth);
    cudaGetSymbolAddress((void**)&ctl, g_ctl);
    cudaGetSymbolAddress((void**)&wh,  g_wh);
    cudaGetSymbolAddress((void**)&wl,  g_wl);
    cudaGetSymbolAddress((void**)&relh, g_relh);
    cudaGetSymbolAddress((void**)&rell, g_rell);

    cudaFuncSetAttribute(attn_tc_kernel, cudaFuncAttributeMaxDynamicSharedMemorySize,
                         ATTN_SMEM);
    cudaFuncSetAttribute(gemm_tc_kernel, cudaFuncAttributeMaxDynamicSharedMemorySize,
                         GEMM_SMEM);

    ln_kernel<<<NTOK, 128>>>(x, gamma, beta);
    split_kernel<<<256, 256>>>(Wq, wh + 0*DD*DD, wl + 0*DD*DD, DD*DD/4);
    split_kernel<<<256, 256>>>(Wk, wh + 1*DD*DD, wl + 1*DD*DD, DD*DD/4);
    split_kernel<<<256, 256>>>(Wv, wh + 2*DD*DD, wl + 2*DD*DD, DD*DD/4);
    split_kernel<<<256, 256>>>(Wo, wh + 3*DD*DD, wl + 3*DD*DD, DD*DD/4);
    split_kernel<<<125, 256>>>(rel, relh, rell, RELN*DKK/4);

    // fused QKV: N = 1536 stacked weights
    dim3 gq(1536 / 128, (NTOK + 127) / 128);  // (12, 63)
    gemm_tc_kernel<<<gq, 256, GEMM_SMEM>>>(xnh, xnl, wh, wl, bq, bk, bv,
                                           nullptr, nullptr,
                                           qh, ql, kh, kl, vh, vl, 0);

    dim3 ga((LL + 63) / 64, BB * HH);  // (16, 64)
    attn_tc_kernel<<<ga, 256, ATTN_SMEM>>>(relh, rell);

    // output projection + residual
    dim3 go(DD / 128, (NTOK + 127) / 128);    // (4, 63)
    gemm_tc_kernel<<<go, 256, GEMM_SMEM>>>(cth, ctl, wh + 3*DD*DD, wl + 3*DD*DD,
                                           bo, nullptr, nullptr,
                                           out, x,
                                           nullptr, nullptr, nullptr, nullptr,
                                           nullptr, nullptr, 1);
}